// round 6
// baseline (speedup 1.0000x reference)
#include <cuda_runtime.h>
#include <math.h>

#define HD     128
#define VOCAB  50000
#define BATCH  128
#define TCC    50
#define TI     32
#define TQ     32
#define NSEQF  (BATCH*TCC)     /* 6400 */
#define G3     (3*HD)          /* 384 */
#define EPISODES 3

// ---------------- static scratch (module-load allocated; no runtime allocs) ----
__device__ __align__(256) float PROJ [VOCAB*G3];     // embed @ ig_Wih^T + ig_bih
__device__ __align__(256) float QGI  [BATCH*TQ*G3];
__device__ __align__(256) float ENCF [NSEQF*HD];
__device__ __align__(256) float QVEC [BATCH*HD];
__device__ __align__(256) float MEMB [BATCH*HD];
__device__ __align__(256) float YQB  [BATCH*2*HD];
__device__ __align__(256) float ATGI [NSEQF*G3];
__device__ __align__(256) float ANGI [BATCH*G3];
__device__ __align__(256) float ZB   [NSEQF*4*HD];
__device__ __align__(256) float UB   [NSEQF*HD];
__device__ __align__(256) float GBUF [NSEQF];
__device__ __align__(256) int   FLENB[NSEQF];
__device__ __align__(256) int   QLENB[BATCH];
__device__ __align__(256) float HDEC [BATCH*32*HD];
__device__ __align__(256) float LSEB [BATCH*32];

__device__ __forceinline__ float sigf(float x) { return 1.f / (1.f + expf(-x)); }

// ---------------- sequence-length kernel -------------------------------------
__global__ void len_kernel(const int* __restrict__ fmask, const int* __restrict__ qmask,
                           int* __restrict__ flen, int* __restrict__ qlen)
{
    int idx = blockIdx.x * blockDim.x + threadIdx.x;
    if (idx < NSEQF) {
        int c = 0;
        #pragma unroll
        for (int t = 0; t < TI; t++) c += (fmask[idx*TI + t] == 0);
        flen[idx] = c;
    } else if (idx < NSEQF + BATCH) {
        int q = idx - NSEQF;
        int c = 0;
        #pragma unroll
        for (int t = 0; t < TQ; t++) c += (qmask[q*TQ + t] == 0);
        qlen[q] = c;
    }
}

// ---------------- generic tiled SGEMM: C = act(A@B^T + bias) ------------------
// A: [M,K] (optionally row-gathered), B: [N,K], C: [M,N]. act: 0=none, 1=tanh
// Requires K % 8 == 0.
__global__ void gemm_kernel(const float* __restrict__ A, const int* __restrict__ gather,
                            const float* __restrict__ B, const float* __restrict__ bias,
                            float* __restrict__ C, int M, int N, int K, int act)
{
    const int BM = 128, BN = 128, BK = 8;
    __shared__ __align__(16) float As[BK][BM];
    __shared__ __align__(16) float Bs[BK][BN];
    int bm = blockIdx.y * BM, bn = blockIdx.x * BN;
    int tid = threadIdx.x;                 // 256 threads
    int tx = tid & 15, ty = tid >> 4;
    int lr = tid >> 1;                     // 0..127
    int lc = (tid & 1) * 4;                // 0 or 4

    float acc[8][8];
    #pragma unroll
    for (int i = 0; i < 8; i++)
        #pragma unroll
        for (int j = 0; j < 8; j++) acc[i][j] = 0.f;

    for (int k0 = 0; k0 < K; k0 += BK) {
        {
            int m = bm + lr;
            float4 v = make_float4(0.f, 0.f, 0.f, 0.f);
            if (m < M) {
                int row = gather ? gather[m] : m;
                v = *(const float4*)(A + (size_t)row * K + k0 + lc);
            }
            As[lc+0][lr] = v.x; As[lc+1][lr] = v.y; As[lc+2][lr] = v.z; As[lc+3][lr] = v.w;
        }
        {
            int n = bn + lr;
            float4 v = make_float4(0.f, 0.f, 0.f, 0.f);
            if (n < N) v = *(const float4*)(B + (size_t)n * K + k0 + lc);
            Bs[lc+0][lr] = v.x; Bs[lc+1][lr] = v.y; Bs[lc+2][lr] = v.z; Bs[lc+3][lr] = v.w;
        }
        __syncthreads();
        #pragma unroll
        for (int k = 0; k < BK; k++) {
            float a[8], b[8];
            *(float4*)&a[0] = *(const float4*)&As[k][ty*8];
            *(float4*)&a[4] = *(const float4*)&As[k][ty*8 + 4];
            *(float4*)&b[0] = *(const float4*)&Bs[k][tx*8];
            *(float4*)&b[4] = *(const float4*)&Bs[k][tx*8 + 4];
            #pragma unroll
            for (int i = 0; i < 8; i++)
                #pragma unroll
                for (int j = 0; j < 8; j++)
                    acc[i][j] = fmaf(a[i], b[j], acc[i][j]);
        }
        __syncthreads();
    }
    #pragma unroll
    for (int i = 0; i < 8; i++) {
        int m = bm + ty*8 + i;
        if (m >= M) continue;
        #pragma unroll
        for (int j = 0; j < 8; j++) {
            int n = bn + tx*8 + j;
            if (n >= N) continue;
            float v = acc[i][j] + (bias ? bias[n] : 0.f);
            if (act == 1) v = tanhf(v);
            C[(size_t)m * N + n] = v;
        }
    }
}

// ---------------- fused multi-step GRU over independent sequences ------------
// gi_tab: PROJ[V][384] indexed by tokens, or precomputed GI[nseq*T][384] when
// tokens == nullptr. Writes h at step (len-1) into encout.
__global__ void gru_seq_kernel(const float* __restrict__ gi_tab, const int* __restrict__ tokens,
                               const float* __restrict__ Whh, const float* __restrict__ bhh,
                               const int* __restrict__ lens, float* __restrict__ encout,
                               int nseq, int T)
{
    const int SG = 8;
    __shared__ __align__(16) float h_sh[SG][HD];
    __shared__ float rr[SG][HD], zz[SG][HD], gin[SG][HD], ghn[SG][HD];
    int g = threadIdx.x;                      // 0..383
    float bh = bhh[g];
    const float4* wr = (const float4*)(Whh + g * HD);

    for (int base = blockIdx.x * SG; base < nseq; base += gridDim.x * SG) {
        for (int i = g; i < SG * HD; i += G3) ((float*)h_sh)[i] = 0.f;
        __syncthreads();
        for (int t = 0; t < T; t++) {
            float gi[SG], gh[SG];
            #pragma unroll
            for (int s = 0; s < SG; s++) {
                int seq = base + s;
                size_t idx;
                if (tokens) {
                    int tok = (seq < nseq) ? tokens[seq*T + t] : 0;
                    idx = (size_t)tok * G3;
                } else {
                    idx = (size_t)((seq < nseq) ? (seq*T + t) : 0) * G3;
                }
                gi[s] = gi_tab[idx + g];
                gh[s] = bh;
            }
            #pragma unroll 8
            for (int kc = 0; kc < HD/4; kc++) {
                float4 w = __ldg(&wr[kc]);
                #pragma unroll
                for (int s = 0; s < SG; s++) {
                    float4 h4 = *(const float4*)&h_sh[s][kc*4];
                    gh[s] = fmaf(w.x, h4.x, gh[s]);
                    gh[s] = fmaf(w.y, h4.y, gh[s]);
                    gh[s] = fmaf(w.z, h4.z, gh[s]);
                    gh[s] = fmaf(w.w, h4.w, gh[s]);
                }
            }
            int j = g & (HD - 1);
            #pragma unroll
            for (int s = 0; s < SG; s++) {
                float v = gi[s] + gh[s];
                if      (g < HD)   rr[s][j] = sigf(v);
                else if (g < 2*HD) zz[s][j] = sigf(v);
                else { gin[s][j] = gi[s]; ghn[s][j] = gh[s]; }
            }
            __syncthreads();
            if (g < HD) {
                #pragma unroll
                for (int s = 0; s < SG; s++) {
                    float r = rr[s][g], z = zz[s][g];
                    float n = tanhf(gin[s][g] + r * ghn[s][g]);
                    float hn = (1.f - z) * n + z * h_sh[s][g];
                    h_sh[s][g] = hn;
                    int seq = base + s;
                    if (seq < nseq) {
                        int L = lens[seq];
                        int tt = (L > 0) ? (L - 1) : 0;
                        if (t == tt) encout[(size_t)seq * HD + g] = hn;
                    }
                }
            }
            __syncthreads();
        }
    }
}

// ---------------- setup: memory init + yq build ------------------------------
__global__ void setup_kernel(const float* __restrict__ embed, const float* __restrict__ qvec,
                             float* __restrict__ mem, float* __restrict__ yq)
{
    int idx = blockIdx.x * blockDim.x + threadIdx.x;
    if (idx >= BATCH * HD) return;
    int b = idx / HD, j = idx % HD;
    float qv = qvec[idx];
    mem[idx] = qv;
    yq[b*2*HD + j]      = embed[2*HD + j];   // <s> embedding (token id 2)
    yq[b*2*HD + HD + j] = qv;
}

// ---------------- gate feature build -----------------------------------------
__global__ void buildz_kernel(const float* __restrict__ encf, const float* __restrict__ q,
                              const float* __restrict__ mem, float* __restrict__ z)
{
    int idx = blockIdx.x * blockDim.x + threadIdx.x;
    if (idx >= NSEQF * 4 * HD) return;
    int row = idx >> 9;          // / 512
    int c   = idx & 511;
    int j   = c & (HD - 1);
    int sel = c >> 7;
    int b   = row / TCC;
    float f  = encf[row*HD + j];
    float qv = q[b*HD + j];
    float mv = mem[b*HD + j];
    float v;
    if      (sel == 0) v = f * qv;
    else if (sel == 1) v = f * mv;
    else if (sel == 2) v = fabsf(f - qv);
    else               v = fabsf(f - mv);
    z[idx] = v;
}

// ---------------- gate reduction: g = sigmoid(u . W2 + b2) --------------------
__global__ void gate_kernel(const float* __restrict__ U, const float* __restrict__ W2,
                            const float* __restrict__ b2, float* __restrict__ G)
{
    int warp = threadIdx.x >> 5, lane = threadIdx.x & 31;
    int row = blockIdx.x * (blockDim.x >> 5) + warp;
    if (row >= NSEQF) return;
    float s = 0.f;
    #pragma unroll
    for (int j = lane; j < HD; j += 32) s += U[(size_t)row*HD + j] * W2[j];
    #pragma unroll
    for (int o = 16; o; o >>= 1) s += __shfl_xor_sync(0xffffffffu, s, o);
    if (lane == 0) G[row] = sigf(s + b2[0]);
}

// ---------------- episode scan (one block per batch element) + memory GRU ----
__global__ void episode_kernel(const float* __restrict__ atgi, const float* __restrict__ gate,
                               const float* __restrict__ Whh, const float* __restrict__ bhh,
                               const float* __restrict__ meWih, const float* __restrict__ meWhh,
                               const float* __restrict__ mebih, const float* __restrict__ mebhh,
                               float* __restrict__ mem)
{
    __shared__ __align__(16) float h_sh[HD];
    __shared__ __align__(16) float msh[HD];
    __shared__ float rr[HD], zz[HD], gin[HD], ghn[HD];
    int b = blockIdx.x, g = threadIdx.x;
    int j = g & (HD - 1);
    if (g < HD) h_sh[g] = 0.f;
    __syncthreads();
    float bh = bhh[g];
    const float4* wr = (const float4*)(Whh + g * HD);

    for (int tc = 0; tc < TCC; tc++) {
        float gi = atgi[(size_t)(b*TCC + tc) * G3 + g];
        float gh = bh;
        #pragma unroll 8
        for (int kc = 0; kc < HD/4; kc++) {
            float4 w = __ldg(&wr[kc]);
            float4 h4 = *(const float4*)&h_sh[kc*4];
            gh = fmaf(w.x, h4.x, gh); gh = fmaf(w.y, h4.y, gh);
            gh = fmaf(w.z, h4.z, gh); gh = fmaf(w.w, h4.w, gh);
        }
        float v = gi + gh;
        if      (g < HD)   rr[j] = sigf(v);
        else if (g < 2*HD) zz[j] = sigf(v);
        else { gin[j] = gi; ghn[j] = gh; }
        __syncthreads();
        if (g < HD) {
            float r = rr[g], z = zz[g];
            float n = tanhf(gin[g] + r * ghn[g]);
            float h2 = (1.f - z) * n + z * h_sh[g];
            float gd = gate[b*TCC + tc];
            h_sh[g] = gd * h2 + (1.f - gd) * h_sh[g];
        }
        __syncthreads();
    }
    // memory = GRUcell(e = h_sh, memory)
    if (g < HD) msh[g] = mem[b*HD + g];
    __syncthreads();
    {
        float gi = mebih[g], gh = mebhh[g];
        const float4* wi = (const float4*)(meWih + g * HD);
        const float4* wh = (const float4*)(meWhh + g * HD);
        #pragma unroll 8
        for (int kc = 0; kc < HD/4; kc++) {
            float4 a = __ldg(&wi[kc]);
            float4 e4 = *(const float4*)&h_sh[kc*4];
            gi = fmaf(a.x, e4.x, gi); gi = fmaf(a.y, e4.y, gi);
            gi = fmaf(a.z, e4.z, gi); gi = fmaf(a.w, e4.w, gi);
            float4 c = __ldg(&wh[kc]);
            float4 m4 = *(const float4*)&msh[kc*4];
            gh = fmaf(c.x, m4.x, gh); gh = fmaf(c.y, m4.y, gh);
            gh = fmaf(c.z, m4.z, gh); gh = fmaf(c.w, m4.w, gh);
        }
        float v = gi + gh;
        if      (g < HD)   rr[j] = sigf(v);
        else if (g < 2*HD) zz[j] = sigf(v);
        else { gin[j] = gi; ghn[j] = gh; }
    }
    __syncthreads();
    if (g < HD) {
        float r = rr[g], z = zz[g];
        float n = tanhf(gin[g] + r * ghn[g]);
        mem[b*HD + g] = (1.f - z) * n + z * msh[g];
    }
}

// ---------------- decoder scan (one block per batch element) ------------------
__global__ void decoder_kernel(const float* __restrict__ angi, const float* __restrict__ Whh,
                               const float* __restrict__ bhh, const float* __restrict__ mem,
                               float* __restrict__ hdec, int Tdec)
{
    __shared__ __align__(16) float h_sh[HD];
    __shared__ float rr[HD], zz[HD], gin[HD], ghn[HD];
    int b = blockIdx.x, g = threadIdx.x;
    int j = g & (HD - 1);
    if (g < HD) h_sh[g] = mem[b*HD + g];
    __syncthreads();
    float gi = angi[(size_t)b * G3 + g];  // constant across steps (yq fixed)
    float bh = bhh[g];
    const float4* wr = (const float4*)(Whh + g * HD);

    for (int t = 0; t < Tdec; t++) {
        float gh = bh;
        #pragma unroll 8
        for (int kc = 0; kc < HD/4; kc++) {
            float4 w = __ldg(&wr[kc]);
            float4 h4 = *(const float4*)&h_sh[kc*4];
            gh = fmaf(w.x, h4.x, gh); gh = fmaf(w.y, h4.y, gh);
            gh = fmaf(w.z, h4.z, gh); gh = fmaf(w.w, h4.w, gh);
        }
        float v = gi + gh;
        if      (g < HD)   rr[j] = sigf(v);
        else if (g < 2*HD) zz[j] = sigf(v);
        else { gin[j] = gi; ghn[j] = gh; }
        __syncthreads();
        if (g < HD) {
            float r = rr[g], z = zz[g];
            float n = tanhf(gin[g] + r * ghn[g]);
            float hn = (1.f - z) * n + z * h_sh[g];
            h_sh[g] = hn;
            hdec[(size_t)(b*Tdec + t) * HD + g] = hn;
        }
        __syncthreads();
    }
}

// ---------------- per-row online logsumexp -----------------------------------
__global__ void lse_kernel(const float* __restrict__ out, float* __restrict__ lse, int V)
{
    __shared__ float sm[256], ss[256];
    int row = blockIdx.x, tid = threadIdx.x;
    const float* x = out + (size_t)row * V;
    float m = -1e30f, s = 0.f;
    for (int i = tid; i < V; i += blockDim.x) {
        float v = x[i];
        if (v > m) { s = s * expf(m - v) + 1.f; m = v; }
        else       { s += expf(v - m); }
    }
    sm[tid] = m; ss[tid] = s;
    __syncthreads();
    for (int o = 128; o; o >>= 1) {
        if (tid < o) {
            float m2 = sm[tid + o], s2 = ss[tid + o];
            float M = fmaxf(sm[tid], m2);
            ss[tid] = ss[tid] * expf(sm[tid] - M) + s2 * expf(m2 - M);
            sm[tid] = M;
        }
        __syncthreads();
    }
    if (tid == 0) lse[row] = sm[0] + logf(ss[0]);
}

__global__ void sub_kernel(float* __restrict__ out, const float* __restrict__ lse, int V)
{
    int row = blockIdx.y;
    int col = blockIdx.x * blockDim.x + threadIdx.x;
    if (col < V) out[(size_t)row * V + col] -= lse[row];
}

// ---------------- host orchestration -----------------------------------------
extern "C" void kernel_launch(void* const* d_in, const int* in_sizes, int n_in,
                              void* d_out, int out_size)
{
    const int*   facts     = (const int*)  d_in[0];
    const int*   fmask     = (const int*)  d_in[1];
    const int*   questions = (const int*)  d_in[2];
    const int*   qmask     = (const int*)  d_in[3];
    /* d_in[4] = num_decode scalar — derived from out_size instead */
    const float* embed  = (const float*)d_in[5];
    const float* igWih  = (const float*)d_in[6],  *igWhh = (const float*)d_in[7];
    const float* igbih  = (const float*)d_in[8],  *igbhh = (const float*)d_in[9];
    const float* qgWih  = (const float*)d_in[10], *qgWhh = (const float*)d_in[11];
    const float* qgbih  = (const float*)d_in[12], *qgbhh = (const float*)d_in[13];
    const float* atWih  = (const float*)d_in[14], *atWhh = (const float*)d_in[15];
    const float* atbih  = (const float*)d_in[16], *atbhh = (const float*)d_in[17];
    const float* meWih  = (const float*)d_in[18], *meWhh = (const float*)d_in[19];
    const float* mebih  = (const float*)d_in[20], *mebhh = (const float*)d_in[21];
    const float* anWih  = (const float*)d_in[22], *anWhh = (const float*)d_in[23];
    const float* anbih  = (const float*)d_in[24], *anbhh = (const float*)d_in[25];
    const float* gateW1 = (const float*)d_in[26], *gateb1 = (const float*)d_in[27];
    const float* gateW2 = (const float*)d_in[28], *gateb2 = (const float*)d_in[29];
    const float* fcW    = (const float*)d_in[30], *fcb    = (const float*)d_in[31];
    float* out = (float*)d_out;

    int Tdec = out_size / (BATCH * VOCAB);
    if (Tdec < 1) Tdec = 1;
    if (Tdec > 32) Tdec = 32;

    float *proj, *qgi, *encf, *qvec, *memb, *yq, *atgi, *angi, *zb, *ub, *gb, *hdec, *lseb;
    int *flen, *qlen;
    cudaGetSymbolAddress((void**)&proj, PROJ);
    cudaGetSymbolAddress((void**)&qgi,  QGI);
    cudaGetSymbolAddress((void**)&encf, ENCF);
    cudaGetSymbolAddress((void**)&qvec, QVEC);
    cudaGetSymbolAddress((void**)&memb, MEMB);
    cudaGetSymbolAddress((void**)&yq,   YQB);
    cudaGetSymbolAddress((void**)&atgi, ATGI);
    cudaGetSymbolAddress((void**)&angi, ANGI);
    cudaGetSymbolAddress((void**)&zb,   ZB);
    cudaGetSymbolAddress((void**)&ub,   UB);
    cudaGetSymbolAddress((void**)&gb,   GBUF);
    cudaGetSymbolAddress((void**)&hdec, HDEC);
    cudaGetSymbolAddress((void**)&lseb, LSEB);
    cudaGetSymbolAddress((void**)&flen, FLENB);
    cudaGetSymbolAddress((void**)&qlen, QLENB);

    // 1) sequence lengths
    len_kernel<<<(NSEQF + BATCH + 255) / 256, 256>>>(fmask, qmask, flen, qlen);

    // 2) PROJ = embed @ ig_Wih^T + ig_bih   (token-level input-projection table)
    {
        dim3 g((G3 + 127) / 128, (VOCAB + 127) / 128);
        gemm_kernel<<<g, 256>>>(embed, nullptr, igWih, igbih, proj, VOCAB, G3, HD, 0);
    }
    // 3) QGI = embed[questions] @ qg_Wih^T + qg_bih (gathered GEMM)
    {
        dim3 g((G3 + 127) / 128, (BATCH*TQ + 127) / 128);
        gemm_kernel<<<g, 256>>>(embed, questions, qgWih, qgbih, qgi, BATCH*TQ, G3, HD, 0);
    }
    // 4) fact + question recurrences (all timesteps inside one kernel each)
    gru_seq_kernel<<<148, G3>>>(proj, facts,   igWhh, igbhh, flen, encf, NSEQF, TI);
    gru_seq_kernel<<<16,  G3>>>(qgi,  nullptr, qgWhh, qgbhh, qlen, qvec, BATCH, TQ);

    // 5) memory = q; yq = [embed[2], q]
    setup_kernel<<<(BATCH*HD + 255) / 256, 256>>>(embed, qvec, memb, yq);

    // 6) ATGI = enc_f @ at_Wih^T + at_bih (reused by all 3 episodes)
    {
        dim3 g((G3 + 127) / 128, (NSEQF + 127) / 128);
        gemm_kernel<<<g, 256>>>(encf, nullptr, atWih, atbih, atgi, NSEQF, G3, HD, 0);
    }
    // 7) ANGI = yq @ an_Wih^T + an_bih (decoder input proj, constant over steps)
    {
        dim3 g((G3 + 127) / 128, 1);
        gemm_kernel<<<g, 256>>>(yq, nullptr, anWih, anbih, angi, BATCH, G3, 2*HD, 0);
    }

    // 8) episodic memory: 3 episodes
    for (int ep = 0; ep < EPISODES; ep++) {
        buildz_kernel<<<(NSEQF*4*HD + 255) / 256, 256>>>(encf, qvec, memb, zb);
        {
            dim3 g((HD + 127) / 128, (NSEQF + 127) / 128);
            gemm_kernel<<<g, 256>>>(zb, nullptr, gateW1, gateb1, ub, NSEQF, HD, 4*HD, 1);
        }
        gate_kernel<<<NSEQF / 8, 256>>>(ub, gateW2, gateb2, gb);
        episode_kernel<<<BATCH, G3>>>(atgi, gb, atWhh, atbhh,
                                      meWih, meWhh, mebih, mebhh, memb);
    }

    // 9) decoder hidden states
    decoder_kernel<<<BATCH, G3>>>(angi, anWhh, anbhh, memb, hdec, Tdec);

    // 10) logits straight into d_out, then log_softmax in place
    {
        dim3 g((VOCAB + 127) / 128, (BATCH*Tdec + 127) / 128);
        gemm_kernel<<<g, 256>>>(hdec, nullptr, fcW, fcb, out, BATCH*Tdec, VOCAB, HD, 0);
    }
    lse_kernel<<<BATCH*Tdec, 256>>>(out, lseb, VOCAB);
    {
        dim3 g((VOCAB + 255) / 256, BATCH*Tdec);
        sub_kernel<<<g, 256>>>(out, lseb, VOCAB);
    }
}

// round 7
// speedup vs baseline: 1.3236x; 1.3236x over previous
#include <cuda_runtime.h>
#include <math.h>

#define HD     128
#define VOCAB  50000
#define BATCH  128
#define TCC    50
#define TI     32
#define TQ     32
#define NSEQF  (BATCH*TCC)     /* 6400 */
#define G3     (3*HD)          /* 384 */
#define EPISODES 3

// GRU smem layout constants
#define WT_STRIDE 388          /* padded row stride for W^T[k][g] */
#define H_STRIDE  129
#define GI_STRIDE 388
#define GRU_SMEM_FLOATS (128*WT_STRIDE + 16*H_STRIDE + 16*GI_STRIDE)
#define GRU_SMEM_BYTES  (GRU_SMEM_FLOATS*4)

// ---------------- static scratch -----------------------------------------
__device__ __align__(256) float PROJ [VOCAB*G3];
__device__ __align__(256) float QGI  [BATCH*TQ*G3];
__device__ __align__(256) float ENCF [NSEQF*HD];
__device__ __align__(256) float QVEC [BATCH*HD];
__device__ __align__(256) float MEMB [BATCH*HD];
__device__ __align__(256) float YQB  [BATCH*2*HD];
__device__ __align__(256) float ATGI [NSEQF*G3];
__device__ __align__(256) float ANGI [BATCH*G3];
__device__ __align__(256) float W1Q  [HD*2*HD];
__device__ __align__(256) float W1M  [HD*2*HD];
__device__ __align__(256) float ZQB  [NSEQF*2*HD];
__device__ __align__(256) float ZMB  [NSEQF*2*HD];
__device__ __align__(256) float UQB  [NSEQF*HD];
__device__ __align__(256) float UB   [NSEQF*HD];
__device__ __align__(256) float GBUF [NSEQF];
__device__ __align__(256) int   FLENB[NSEQF];
__device__ __align__(256) int   QLENB[BATCH];
__device__ __align__(256) float HDEC [BATCH*32*HD];
__device__ __align__(256) float LSEB [BATCH*32];

__device__ __forceinline__ float sigf(float x) { return 1.f / (1.f + expf(-x)); }

// ---------------- sequence lengths ----------------------------------------
__global__ void len_kernel(const int* __restrict__ fmask, const int* __restrict__ qmask,
                           int* __restrict__ flen, int* __restrict__ qlen)
{
    int idx = blockIdx.x * blockDim.x + threadIdx.x;
    if (idx < NSEQF) {
        int c = 0;
        #pragma unroll
        for (int t = 0; t < TI; t++) c += (fmask[idx*TI + t] == 0);
        flen[idx] = c;
    } else if (idx < NSEQF + BATCH) {
        int q = idx - NSEQF;
        int c = 0;
        #pragma unroll
        for (int t = 0; t < TQ; t++) c += (qmask[q*TQ + t] == 0);
        qlen[q] = c;
    }
}

// ---------------- tiled SGEMM: C = act(A@B^T + bias + addC) ---------------
// A:[M,K] (optional row gather), B:[N,K], C:[M,N]. K % 16 == 0. act 1 = tanh.
__global__ void gemm_kernel(const float* __restrict__ A, const int* __restrict__ gather,
                            const float* __restrict__ B, const float* __restrict__ bias,
                            const float* __restrict__ addC, float* __restrict__ C,
                            int M, int N, int K, int act)
{
    const int BM = 128, BN = 128, BK = 16;
    __shared__ __align__(16) float As[BK][BM];
    __shared__ __align__(16) float Bs[BK][BN];
    int bm = blockIdx.y * BM, bn = blockIdx.x * BN;
    int tid = threadIdx.x;                 // 256 threads
    int tx = tid & 15, ty = tid >> 4;
    int lr = tid >> 1;                     // 0..127 (row)
    int lk = (tid & 1) * 4;                // 0 or 4

    float acc[8][8];
    #pragma unroll
    for (int i = 0; i < 8; i++)
        #pragma unroll
        for (int j = 0; j < 8; j++) acc[i][j] = 0.f;

    for (int k0 = 0; k0 < K; k0 += BK) {
        {
            int m = bm + lr;
            float4 v0 = make_float4(0.f,0.f,0.f,0.f), v1 = v0;
            if (m < M) {
                int row = gather ? gather[m] : m;
                const float* ap = A + (size_t)row * K + k0;
                v0 = *(const float4*)(ap + lk);
                v1 = *(const float4*)(ap + lk + 8);
            }
            As[lk+0][lr]=v0.x; As[lk+1][lr]=v0.y; As[lk+2][lr]=v0.z; As[lk+3][lr]=v0.w;
            As[lk+8][lr]=v1.x; As[lk+9][lr]=v1.y; As[lk+10][lr]=v1.z; As[lk+11][lr]=v1.w;
        }
        {
            int n = bn + lr;
            float4 v0 = make_float4(0.f,0.f,0.f,0.f), v1 = v0;
            if (n < N) {
                const float* bp = B + (size_t)n * K + k0;
                v0 = *(const float4*)(bp + lk);
                v1 = *(const float4*)(bp + lk + 8);
            }
            Bs[lk+0][lr]=v0.x; Bs[lk+1][lr]=v0.y; Bs[lk+2][lr]=v0.z; Bs[lk+3][lr]=v0.w;
            Bs[lk+8][lr]=v1.x; Bs[lk+9][lr]=v1.y; Bs[lk+10][lr]=v1.z; Bs[lk+11][lr]=v1.w;
        }
        __syncthreads();
        #pragma unroll
        for (int k = 0; k < BK; k++) {
            float a[8], b[8];
            *(float4*)&a[0] = *(const float4*)&As[k][ty*8];
            *(float4*)&a[4] = *(const float4*)&As[k][ty*8 + 4];
            *(float4*)&b[0] = *(const float4*)&Bs[k][tx*8];
            *(float4*)&b[4] = *(const float4*)&Bs[k][tx*8 + 4];
            #pragma unroll
            for (int i = 0; i < 8; i++)
                #pragma unroll
                for (int j = 0; j < 8; j++)
                    acc[i][j] = fmaf(a[i], b[j], acc[i][j]);
        }
        __syncthreads();
    }
    #pragma unroll
    for (int i = 0; i < 8; i++) {
        int m = bm + ty*8 + i;
        if (m >= M) continue;
        #pragma unroll
        for (int j = 0; j < 8; j++) {
            int n = bn + tx*8 + j;
            if (n >= N) continue;
            float v = acc[i][j];
            if (bias) v += bias[n];
            if (addC) v += addC[(size_t)m * N + j + (bn + tx*8)];
            if (act == 1) v = tanhf(v);
            C[(size_t)m * N + n] = v;
        }
    }
}

// ---------------- weight-stationary multi-step GRU -------------------------
// 16 sequences per block, Whh^T resident in smem, 256 threads.
// gi_tab: PROJ gathered by tokens, or dense GI rows (tokens==nullptr).
__global__ __launch_bounds__(256)
void gru_seq2_kernel(const float* __restrict__ gi_tab, const int* __restrict__ tokens,
                     const float* __restrict__ Whh, const float* __restrict__ bhh,
                     const int* __restrict__ lens, float* __restrict__ encout, int T)
{
    extern __shared__ float sm[];
    float* WT   = sm;                          // [128][WT_STRIDE]
    float* hsh  = WT  + 128*WT_STRIDE;         // [16][H_STRIDE]
    float* gish = hsh + 16*H_STRIDE;           // [16][GI_STRIDE]
    __shared__ int len_sh[16];

    int tid = threadIdx.x;
    int base = blockIdx.x * 16;

    // load Whh transposed into smem: WT[k][g] = Whh[g][k]
    for (int idx = tid; idx < 384*32; idx += 256) {
        int g  = idx % 384;
        int k4 = idx / 384;
        float4 v = *(const float4*)(Whh + (size_t)g*HD + k4*4);
        WT[(k4*4+0)*WT_STRIDE + g] = v.x;
        WT[(k4*4+1)*WT_STRIDE + g] = v.y;
        WT[(k4*4+2)*WT_STRIDE + g] = v.z;
        WT[(k4*4+3)*WT_STRIDE + g] = v.w;
    }
    for (int i = tid; i < 16*H_STRIDE; i += 256) hsh[i] = 0.f;
    if (tid < 16) len_sh[tid] = lens[base + tid];
    __syncthreads();

    int jgrp = tid >> 3;           // 0..31
    int sgrp = tid & 7;            // 0..7
    int j0 = jgrp * 4;
    int s0 = sgrp * 2;

    float br[4], bz[4], bn_[4];
    #pragma unroll
    for (int i = 0; i < 4; i++) {
        br[i]  = bhh[j0 + i];
        bz[i]  = bhh[HD + j0 + i];
        bn_[i] = bhh[2*HD + j0 + i];
    }

    for (int t = 0; t < T; t++) {
        // stage gi[s][0..383] (coalesced row copies)
        for (int i = tid; i < 16*96; i += 256) {
            int s = i / 96, c4 = i % 96;
            size_t srow;
            if (tokens) {
                int tok = tokens[(size_t)(base + s) * T + t];
                srow = (size_t)tok * G3;
            } else {
                srow = (size_t)((base + s) * T + t) * G3;
            }
            *(float4*)(gish + s*GI_STRIDE + c4*4) =
                *(const float4*)(gi_tab + srow + c4*4);
        }

        // gh = Whh . h  (register-tiled)
        float ar00=0.f,ar01=0.f,ar10=0.f,ar11=0.f,ar20=0.f,ar21=0.f,ar30=0.f,ar31=0.f;
        float az00=0.f,az01=0.f,az10=0.f,az11=0.f,az20=0.f,az21=0.f,az30=0.f,az31=0.f;
        float an00=0.f,an01=0.f,an10=0.f,an11=0.f,an20=0.f,an21=0.f,an30=0.f,an31=0.f;
        const float* hp0 = hsh + s0*H_STRIDE;
        const float* hp1 = hsh + (s0+1)*H_STRIDE;
        #pragma unroll 4
        for (int k = 0; k < HD; k++) {
            const float* wrow = WT + k*WT_STRIDE;
            float4 wr = *(const float4*)(wrow + j0);
            float4 wz = *(const float4*)(wrow + HD + j0);
            float4 wn = *(const float4*)(wrow + 2*HD + j0);
            float h0 = hp0[k], h1 = hp1[k];
            ar00 = fmaf(wr.x, h0, ar00); ar01 = fmaf(wr.x, h1, ar01);
            ar10 = fmaf(wr.y, h0, ar10); ar11 = fmaf(wr.y, h1, ar11);
            ar20 = fmaf(wr.z, h0, ar20); ar21 = fmaf(wr.z, h1, ar21);
            ar30 = fmaf(wr.w, h0, ar30); ar31 = fmaf(wr.w, h1, ar31);
            az00 = fmaf(wz.x, h0, az00); az01 = fmaf(wz.x, h1, az01);
            az10 = fmaf(wz.y, h0, az10); az11 = fmaf(wz.y, h1, az11);
            az20 = fmaf(wz.z, h0, az20); az21 = fmaf(wz.z, h1, az21);
            az30 = fmaf(wz.w, h0, az30); az31 = fmaf(wz.w, h1, az31);
            an00 = fmaf(wn.x, h0, an00); an01 = fmaf(wn.x, h1, an01);
            an10 = fmaf(wn.y, h0, an10); an11 = fmaf(wn.y, h1, an11);
            an20 = fmaf(wn.z, h0, an20); an21 = fmaf(wn.z, h1, an21);
            an30 = fmaf(wn.w, h0, an30); an31 = fmaf(wn.w, h1, an31);
        }
        __syncthreads();   // gi staged; all h reads done

        // pointwise update (each thread owns its (j, s) pairs)
        float accr[4][2] = {{ar00,ar01},{ar10,ar11},{ar20,ar21},{ar30,ar31}};
        float accz[4][2] = {{az00,az01},{az10,az11},{az20,az21},{az30,az31}};
        float accn[4][2] = {{an00,an01},{an10,an11},{an20,an21},{an30,an31}};
        #pragma unroll
        for (int si = 0; si < 2; si++) {
            int s = s0 + si;
            float* hrow = hsh + s*H_STRIDE;
            const float* girow = gish + s*GI_STRIDE;
            int L = len_sh[s];
            int tlast = (L > 0) ? (L - 1) : 0;
            #pragma unroll
            for (int ji = 0; ji < 4; ji++) {
                int j = j0 + ji;
                float r = sigf(girow[j]        + accr[ji][si] + br[ji]);
                float z = sigf(girow[HD + j]   + accz[ji][si] + bz[ji]);
                float n = tanhf(girow[2*HD + j] + r * (accn[ji][si] + bn_[ji]));
                float hold = hrow[j];
                float hnew = (1.f - z) * n + z * hold;
                hrow[j] = hnew;
                if (t == tlast) encout[(size_t)(base + s) * HD + j] = hnew;
            }
        }
        __syncthreads();
    }
}

// ---------------- setup: memory init + yq build ----------------------------
__global__ void setup_kernel(const float* __restrict__ embed, const float* __restrict__ qvec,
                             float* __restrict__ mem, float* __restrict__ yq)
{
    int idx = blockIdx.x * blockDim.x + threadIdx.x;
    if (idx >= BATCH * HD) return;
    int b = idx / HD, j = idx % HD;
    float qv = qvec[idx];
    mem[idx] = qv;
    yq[b*2*HD + j]      = embed[2*HD + j];
    yq[b*2*HD + HD + j] = qv;
}

// ---------------- gate-path preprocessing ----------------------------------
__global__ void repack_w1_kernel(const float* __restrict__ W1,
                                 float* __restrict__ W1q, float* __restrict__ W1m)
{
    int idx = blockIdx.x * blockDim.x + threadIdx.x;
    if (idx >= HD * 2*HD) return;
    int o = idx >> 8, c = idx & 255;
    int cq = (c < HD) ? c : (2*HD + (c - HD));
    int cm = (c < HD) ? (HD + c) : (3*HD + (c - HD));
    W1q[idx] = W1[o*4*HD + cq];
    W1m[idx] = W1[o*4*HD + cm];
}

__global__ void buildzq_kernel(const float* __restrict__ encf, const float* __restrict__ q,
                               float* __restrict__ zq)
{
    int idx = blockIdx.x * blockDim.x + threadIdx.x;
    if (idx >= NSEQF * 2*HD) return;
    int row = idx >> 8, c = idx & 255, j = c & (HD-1), b = row / TCC;
    float f  = encf[row*HD + j];
    float qv = q[b*HD + j];
    zq[idx] = (c < HD) ? f * qv : fabsf(f - qv);
}

__global__ void buildzm_kernel(const float* __restrict__ encf, const float* __restrict__ mem,
                               float* __restrict__ zm)
{
    int idx = blockIdx.x * blockDim.x + threadIdx.x;
    if (idx >= NSEQF * 2*HD) return;
    int row = idx >> 8, c = idx & 255, j = c & (HD-1), b = row / TCC;
    float f  = encf[row*HD + j];
    float mv = mem[b*HD + j];
    zm[idx] = (c < HD) ? f * mv : fabsf(f - mv);
}

// ---------------- gate reduction -------------------------------------------
__global__ void gate_kernel(const float* __restrict__ U, const float* __restrict__ W2,
                            const float* __restrict__ b2, float* __restrict__ G)
{
    int warp = threadIdx.x >> 5, lane = threadIdx.x & 31;
    int row = blockIdx.x * (blockDim.x >> 5) + warp;
    if (row >= NSEQF) return;
    float s = 0.f;
    #pragma unroll
    for (int j = lane; j < HD; j += 32) s += U[(size_t)row*HD + j] * W2[j];
    #pragma unroll
    for (int o = 16; o; o >>= 1) s += __shfl_xor_sync(0xffffffffu, s, o);
    if (lane == 0) G[row] = sigf(s + b2[0]);
}

// ---------------- episode scan + memory GRU --------------------------------
__global__ void episode_kernel(const float* __restrict__ atgi, const float* __restrict__ gate,
                               const float* __restrict__ Whh, const float* __restrict__ bhh,
                               const float* __restrict__ meWih, const float* __restrict__ meWhh,
                               const float* __restrict__ mebih, const float* __restrict__ mebhh,
                               float* __restrict__ mem)
{
    __shared__ __align__(16) float h_sh[HD];
    __shared__ __align__(16) float msh[HD];
    __shared__ float rr[HD], zz[HD], gin[HD], ghn[HD];
    int b = blockIdx.x, g = threadIdx.x;
    int j = g & (HD - 1);
    if (g < HD) h_sh[g] = 0.f;
    __syncthreads();
    float bh = bhh[g];
    const float4* wr = (const float4*)(Whh + g * HD);

    for (int tc = 0; tc < TCC; tc++) {
        float gi = atgi[(size_t)(b*TCC + tc) * G3 + g];
        float gh = bh;
        #pragma unroll 8
        for (int kc = 0; kc < HD/4; kc++) {
            float4 w = __ldg(&wr[kc]);
            float4 h4 = *(const float4*)&h_sh[kc*4];
            gh = fmaf(w.x, h4.x, gh); gh = fmaf(w.y, h4.y, gh);
            gh = fmaf(w.z, h4.z, gh); gh = fmaf(w.w, h4.w, gh);
        }
        float v = gi + gh;
        if      (g < HD)   rr[j] = sigf(v);
        else if (g < 2*HD) zz[j] = sigf(v);
        else { gin[j] = gi; ghn[j] = gh; }
        __syncthreads();
        if (g < HD) {
            float r = rr[g], z = zz[g];
            float n = tanhf(gin[g] + r * ghn[g]);
            float h2 = (1.f - z) * n + z * h_sh[g];
            float gd = gate[b*TCC + tc];
            h_sh[g] = gd * h2 + (1.f - gd) * h_sh[g];
        }
        __syncthreads();
    }
    if (g < HD) msh[g] = mem[b*HD + g];
    __syncthreads();
    {
        float gi = mebih[g], gh = mebhh[g];
        const float4* wi = (const float4*)(meWih + g * HD);
        const float4* wh = (const float4*)(meWhh + g * HD);
        #pragma unroll 8
        for (int kc = 0; kc < HD/4; kc++) {
            float4 a = __ldg(&wi[kc]);
            float4 e4 = *(const float4*)&h_sh[kc*4];
            gi = fmaf(a.x, e4.x, gi); gi = fmaf(a.y, e4.y, gi);
            gi = fmaf(a.z, e4.z, gi); gi = fmaf(a.w, e4.w, gi);
            float4 c = __ldg(&wh[kc]);
            float4 m4 = *(const float4*)&msh[kc*4];
            gh = fmaf(c.x, m4.x, gh); gh = fmaf(c.y, m4.y, gh);
            gh = fmaf(c.z, m4.z, gh); gh = fmaf(c.w, m4.w, gh);
        }
        float v = gi + gh;
        if      (g < HD)   rr[j] = sigf(v);
        else if (g < 2*HD) zz[j] = sigf(v);
        else { gin[j] = gi; ghn[j] = gh; }
    }
    __syncthreads();
    if (g < HD) {
        float r = rr[g], z = zz[g];
        float n = tanhf(gin[g] + r * ghn[g]);
        mem[b*HD + g] = (1.f - z) * n + z * msh[g];
    }
}

// ---------------- decoder scan ---------------------------------------------
__global__ void decoder_kernel(const float* __restrict__ angi, const float* __restrict__ Whh,
                               const float* __restrict__ bhh, const float* __restrict__ mem,
                               float* __restrict__ hdec, int Tdec)
{
    __shared__ __align__(16) float h_sh[HD];
    __shared__ float rr[HD], zz[HD], gin[HD], ghn[HD];
    int b = blockIdx.x, g = threadIdx.x;
    int j = g & (HD - 1);
    if (g < HD) h_sh[g] = mem[b*HD + g];
    __syncthreads();
    float gi = angi[(size_t)b * G3 + g];
    float bh = bhh[g];
    const float4* wr = (const float4*)(Whh + g * HD);

    for (int t = 0; t < Tdec; t++) {
        float gh = bh;
        #pragma unroll 8
        for (int kc = 0; kc < HD/4; kc++) {
            float4 w = __ldg(&wr[kc]);
            float4 h4 = *(const float4*)&h_sh[kc*4];
            gh = fmaf(w.x, h4.x, gh); gh = fmaf(w.y, h4.y, gh);
            gh = fmaf(w.z, h4.z, gh); gh = fmaf(w.w, h4.w, gh);
        }
        float v = gi + gh;
        if      (g < HD)   rr[j] = sigf(v);
        else if (g < 2*HD) zz[j] = sigf(v);
        else { gin[j] = gi; ghn[j] = gh; }
        __syncthreads();
        if (g < HD) {
            float r = rr[g], z = zz[g];
            float n = tanhf(gin[g] + r * ghn[g]);
            float hn = (1.f - z) * n + z * h_sh[g];
            h_sh[g] = hn;
            hdec[(size_t)(b*Tdec + t) * HD + g] = hn;
        }
        __syncthreads();
    }
}

// ---------------- per-row online logsumexp + subtract -----------------------
__global__ void lse_kernel(const float* __restrict__ out, float* __restrict__ lse, int V)
{
    __shared__ float sm[256], ss[256];
    int row = blockIdx.x, tid = threadIdx.x;
    const float* x = out + (size_t)row * V;
    float m = -1e30f, s = 0.f;
    for (int i = tid; i < V; i += blockDim.x) {
        float v = x[i];
        if (v > m) { s = s * expf(m - v) + 1.f; m = v; }
        else       { s += expf(v - m); }
    }
    sm[tid] = m; ss[tid] = s;
    __syncthreads();
    for (int o = 128; o; o >>= 1) {
        if (tid < o) {
            float m2 = sm[tid + o], s2 = ss[tid + o];
            float M = fmaxf(sm[tid], m2);
            ss[tid] = ss[tid] * expf(sm[tid] - M) + s2 * expf(m2 - M);
            sm[tid] = M;
        }
        __syncthreads();
    }
    if (tid == 0) lse[row] = sm[0] + logf(ss[0]);
}

__global__ void sub_kernel(float* __restrict__ out, const float* __restrict__ lse, int V)
{
    int row = blockIdx.y;
    int col = blockIdx.x * blockDim.x + threadIdx.x;
    if (col < V) out[(size_t)row * V + col] -= lse[row];
}

// ---------------- host orchestration ---------------------------------------
extern "C" void kernel_launch(void* const* d_in, const int* in_sizes, int n_in,
                              void* d_out, int out_size)
{
    const int*   facts     = (const int*)  d_in[0];
    const int*   fmask     = (const int*)  d_in[1];
    const int*   questions = (const int*)  d_in[2];
    const int*   qmask     = (const int*)  d_in[3];
    const float* embed  = (const float*)d_in[5];
    const float* igWih  = (const float*)d_in[6],  *igWhh = (const float*)d_in[7];
    const float* igbih  = (const float*)d_in[8],  *igbhh = (const float*)d_in[9];
    const float* qgWih  = (const float*)d_in[10], *qgWhh = (const float*)d_in[11];
    const float* qgbih  = (const float*)d_in[12], *qgbhh = (const float*)d_in[13];
    const float* atWih  = (const float*)d_in[14], *atWhh = (const float*)d_in[15];
    const float* atbih  = (const float*)d_in[16], *atbhh = (const float*)d_in[17];
    const float* meWih  = (const float*)d_in[18], *meWhh = (const float*)d_in[19];
    const float* mebih  = (const float*)d_in[20], *mebhh = (const float*)d_in[21];
    const float* anWih  = (const float*)d_in[22], *anWhh = (const float*)d_in[23];
    const float* anbih  = (const float*)d_in[24], *anbhh = (const float*)d_in[25];
    const float* gateW1 = (const float*)d_in[26], *gateb1 = (const float*)d_in[27];
    const float* gateW2 = (const float*)d_in[28], *gateb2 = (const float*)d_in[29];
    const float* fcW    = (const float*)d_in[30], *fcb    = (const float*)d_in[31];
    float* out = (float*)d_out;

    int Tdec = out_size / (BATCH * VOCAB);
    if (Tdec < 1) Tdec = 1;
    if (Tdec > 32) Tdec = 32;

    float *proj, *qgi, *encf, *qvec, *memb, *yq, *atgi, *angi;
    float *w1q, *w1m, *zq, *zm, *uq, *ub, *gb, *hdec, *lseb;
    int *flen, *qlen;
    cudaGetSymbolAddress((void**)&proj, PROJ);
    cudaGetSymbolAddress((void**)&qgi,  QGI);
    cudaGetSymbolAddress((void**)&encf, ENCF);
    cudaGetSymbolAddress((void**)&qvec, QVEC);
    cudaGetSymbolAddress((void**)&memb, MEMB);
    cudaGetSymbolAddress((void**)&yq,   YQB);
    cudaGetSymbolAddress((void**)&atgi, ATGI);
    cudaGetSymbolAddress((void**)&angi, ANGI);
    cudaGetSymbolAddress((void**)&w1q,  W1Q);
    cudaGetSymbolAddress((void**)&w1m,  W1M);
    cudaGetSymbolAddress((void**)&zq,   ZQB);
    cudaGetSymbolAddress((void**)&zm,   ZMB);
    cudaGetSymbolAddress((void**)&uq,   UQB);
    cudaGetSymbolAddress((void**)&ub,   UB);
    cudaGetSymbolAddress((void**)&gb,   GBUF);
    cudaGetSymbolAddress((void**)&hdec, HDEC);
    cudaGetSymbolAddress((void**)&lseb, LSEB);
    cudaGetSymbolAddress((void**)&flen, FLENB);
    cudaGetSymbolAddress((void**)&qlen, QLENB);

    cudaFuncSetAttribute(gru_seq2_kernel,
                         cudaFuncAttributeMaxDynamicSharedMemorySize, GRU_SMEM_BYTES);

    // 1) sequence lengths
    len_kernel<<<(NSEQF + BATCH + 255) / 256, 256>>>(fmask, qmask, flen, qlen);

    // 2) PROJ = embed @ ig_Wih^T + ig_bih
    {
        dim3 g((G3 + 127) / 128, (VOCAB + 127) / 128);
        gemm_kernel<<<g, 256>>>(embed, nullptr, igWih, igbih, nullptr, proj, VOCAB, G3, HD, 0);
    }
    // 3) QGI = embed[questions] @ qg_Wih^T + qg_bih
    {
        dim3 g((G3 + 127) / 128, (BATCH*TQ + 127) / 128);
        gemm_kernel<<<g, 256>>>(embed, questions, qgWih, qgbih, nullptr, qgi, BATCH*TQ, G3, HD, 0);
    }
    // 4) fact + question recurrences (weight-stationary smem GRU)
    gru_seq2_kernel<<<NSEQF/16, 256, GRU_SMEM_BYTES>>>(proj, facts, igWhh, igbhh, flen, encf, TI);
    gru_seq2_kernel<<<BATCH/16, 256, GRU_SMEM_BYTES>>>(qgi, nullptr, qgWhh, qgbhh, qlen, qvec, TQ);

    // 5) memory = q; yq = [embed[2], q]
    setup_kernel<<<(BATCH*HD + 255) / 256, 256>>>(embed, qvec, memb, yq);

    // 6) ATGI = enc_f @ at_Wih^T + at_bih
    {
        dim3 g((G3 + 127) / 128, (NSEQF + 127) / 128);
        gemm_kernel<<<g, 256>>>(encf, nullptr, atWih, atbih, nullptr, atgi, NSEQF, G3, HD, 0);
    }
    // 7) ANGI = yq @ an_Wih^T + an_bih
    {
        dim3 g((G3 + 127) / 128, 1);
        gemm_kernel<<<g, 256>>>(yq, nullptr, anWih, anbih, nullptr, angi, BATCH, G3, 2*HD, 0);
    }

    // 8) gate path: episode-invariant half computed once
    repack_w1_kernel<<<(HD*2*HD + 255) / 256, 256>>>(gateW1, w1q, w1m);
    buildzq_kernel<<<(NSEQF*2*HD + 255) / 256, 256>>>(encf, qvec, zq);
    {
        dim3 g((HD + 127) / 128, (NSEQF + 127) / 128);
        gemm_kernel<<<g, 256>>>(zq, nullptr, w1q, nullptr, nullptr, uq, NSEQF, HD, 2*HD, 0);
    }

    // 9) episodic memory: 3 episodes
    for (int ep = 0; ep < EPISODES; ep++) {
        buildzm_kernel<<<(NSEQF*2*HD + 255) / 256, 256>>>(encf, memb, zm);
        {
            dim3 g((HD + 127) / 128, (NSEQF + 127) / 128);
            gemm_kernel<<<g, 256>>>(zm, nullptr, w1m, gateb1, uq, ub, NSEQF, HD, 2*HD, 1);
        }
        gate_kernel<<<NSEQF / 8, 256>>>(ub, gateW2, gateb2, gb);
        episode_kernel<<<BATCH, G3>>>(atgi, gb, atWhh, atbhh,
                                      meWih, meWhh, mebih, mebhh, memb);
    }

    // 10) decoder hidden states
    decoder_kernel<<<BATCH, G3>>>(angi, anWhh, anbhh, memb, hdec, Tdec);

    // 11) logits into d_out + log_softmax in place
    {
        dim3 g((VOCAB + 127) / 128, (BATCH*Tdec + 127) / 128);
        gemm_kernel<<<g, 256>>>(hdec, nullptr, fcW, fcb, nullptr, out, BATCH*Tdec, VOCAB, HD, 0);
    }
    lse_kernel<<<BATCH*Tdec, 256>>>(out, lseb, VOCAB);
    {
        dim3 g((VOCAB + 255) / 256, BATCH*Tdec);
        sub_kernel<<<g, 256>>>(out, lseb, VOCAB);
    }
}

// round 8
// speedup vs baseline: 1.8379x; 1.3885x over previous
#include <cuda_runtime.h>
#include <cuda_bf16.h>
#include <math.h>

#define HD     128
#define VOCAB  50000
#define BATCH  128
#define TCC    50
#define TI     32
#define TQ     32
#define NSEQF  (BATCH*TCC)     /* 6400 */
#define G3     (3*HD)          /* 384 */
#define EPISODES 3

// GRU smem layout constants
#define WT_STRIDE 388
#define H_STRIDE  129
#define GI_STRIDE 388
#define GRU_SMEM_FLOATS (128*WT_STRIDE + 16*H_STRIDE + 16*GI_STRIDE)
#define GRU_SMEM_BYTES  (GRU_SMEM_FLOATS*4)

// bgemm smem stride (halves): 72 halves = 144B = 36 words -> conflict-free
#define AS_H 72

// ---------------- static scratch -----------------------------------------
__device__ __align__(256) float PROJ [VOCAB*G3];
__device__ __align__(256) float QGI  [BATCH*TQ*G3];
__device__ __align__(256) float ENCF [NSEQF*HD];
__device__ __align__(256) float QVEC [BATCH*HD];
__device__ __align__(256) float MEMB [BATCH*HD];
__device__ __align__(256) float YQB  [BATCH*2*HD];
__device__ __align__(256) float ATGI [NSEQF*G3];
__device__ __align__(256) float ANGI [BATCH*G3];
__device__ __align__(256) float UQB  [NSEQF*HD];
__device__ __align__(256) float UB   [NSEQF*HD];
__device__ __align__(256) float GBUF [NSEQF];
__device__ __align__(256) int   FLENB[NSEQF];
__device__ __align__(256) int   QLENB[BATCH];
__device__ __align__(256) float HDEC [BATCH*32*HD];

// bf16 scratch
__device__ __align__(256) __nv_bfloat16 EMB16 [VOCAB*HD];
__device__ __align__(256) __nv_bfloat16 IGW16 [G3*HD];
__device__ __align__(256) __nv_bfloat16 QGW16 [G3*HD];
__device__ __align__(256) __nv_bfloat16 ATW16 [G3*HD];
__device__ __align__(256) __nv_bfloat16 FCW16 [VOCAB*HD];
__device__ __align__(256) __nv_bfloat16 ENCF16[NSEQF*HD];
__device__ __align__(256) __nv_bfloat16 HDEC16[BATCH*32*HD];
__device__ __align__(256) __nv_bfloat16 ZQ16  [NSEQF*2*HD];
__device__ __align__(256) __nv_bfloat16 ZM16  [NSEQF*2*HD];
__device__ __align__(256) __nv_bfloat16 W1Q16 [HD*2*HD];
__device__ __align__(256) __nv_bfloat16 W1M16 [HD*2*HD];

__device__ __forceinline__ float sigf(float x) { return 1.f / (1.f + expf(-x)); }

// ---------------- f32 -> bf16 convert (vectorized) -------------------------
__global__ void cvt_kernel(const float* __restrict__ src, __nv_bfloat16* __restrict__ dst, int n4)
{
    int i = blockIdx.x * blockDim.x + threadIdx.x;
    if (i >= n4) return;
    float4 v = *(const float4*)(src + i*4);
    __nv_bfloat16 o[4];
    o[0] = __float2bfloat16(v.x); o[1] = __float2bfloat16(v.y);
    o[2] = __float2bfloat16(v.z); o[3] = __float2bfloat16(v.w);
    *(uint2*)(dst + i*4) = *(uint2*)o;
}

// ---------------- sequence lengths ----------------------------------------
__global__ void len_kernel(const int* __restrict__ fmask, const int* __restrict__ qmask,
                           int* __restrict__ flen, int* __restrict__ qlen)
{
    int idx = blockIdx.x * blockDim.x + threadIdx.x;
    if (idx < NSEQF) {
        int c = 0;
        #pragma unroll
        for (int t = 0; t < TI; t++) c += (fmask[idx*TI + t] == 0);
        flen[idx] = c;
    } else if (idx < NSEQF + BATCH) {
        int q = idx - NSEQF;
        int c = 0;
        #pragma unroll
        for (int t = 0; t < TQ; t++) c += (qmask[q*TQ + t] == 0);
        qlen[q] = c;
    }
}

// ---------------- bf16 tensor-core GEMM: C = act(A@B^T + bias + addC) ------
// A:[M,K] bf16 (optional row gather), B:[N,K] bf16, C:[M,N] fp32.
// K % 32 == 0. act 1 = tanh. addC:[M,N] fp32 or null.
__global__ __launch_bounds__(256)
void bgemm_kernel(const __nv_bfloat16* __restrict__ A, const int* __restrict__ gather,
                  const __nv_bfloat16* __restrict__ B, const float* __restrict__ bias,
                  const float* __restrict__ addC, float* __restrict__ C,
                  int M, int N, int K, int act)
{
    __shared__ __align__(16) __nv_bfloat16 As[128*AS_H];
    __shared__ __align__(16) __nv_bfloat16 Bs[128*AS_H];
    int bm = blockIdx.y * 128, bn = blockIdx.x * 128;
    int tid = threadIdx.x;
    int warp = tid >> 5, lane = tid & 31;
    int g = lane >> 2, tg = lane & 3;
    int wm = (warp >> 2) * 64, wn = (warp & 3) * 32;

    float acc[4][4][4];
    #pragma unroll
    for (int mi = 0; mi < 4; mi++)
        #pragma unroll
        for (int ni = 0; ni < 4; ni++)
            #pragma unroll
            for (int r = 0; r < 4; r++) acc[mi][ni][r] = 0.f;

    for (int k0 = 0; k0 < K; k0 += 32) {
        #pragma unroll
        for (int c = 0; c < 2; c++) {
            int chunk = tid + 256*c;
            int row = chunk >> 2, kc = chunk & 3;
            int m = bm + row;
            uint4 v = make_uint4(0,0,0,0);
            if (m < M) {
                int ar = gather ? gather[m] : m;
                v = *(const uint4*)(A + (size_t)ar * K + k0 + kc*8);
            }
            *(uint4*)(As + row*AS_H + kc*8) = v;
        }
        #pragma unroll
        for (int c = 0; c < 2; c++) {
            int chunk = tid + 256*c;
            int row = chunk >> 2, kc = chunk & 3;
            int n = bn + row;
            uint4 v = make_uint4(0,0,0,0);
            if (n < N) v = *(const uint4*)(B + (size_t)n * K + k0 + kc*8);
            *(uint4*)(Bs + row*AS_H + kc*8) = v;
        }
        __syncthreads();
        #pragma unroll
        for (int ka = 0; ka < 2; ka++) {
            unsigned afr[4][4], bfr[4][2];
            #pragma unroll
            for (int mi = 0; mi < 4; mi++) {
                const __nv_bfloat16* ap = As + (wm + mi*16)*AS_H + ka*16;
                afr[mi][0] = *(const unsigned*)(ap + g*AS_H + tg*2);
                afr[mi][1] = *(const unsigned*)(ap + (g+8)*AS_H + tg*2);
                afr[mi][2] = *(const unsigned*)(ap + g*AS_H + 8 + tg*2);
                afr[mi][3] = *(const unsigned*)(ap + (g+8)*AS_H + 8 + tg*2);
            }
            #pragma unroll
            for (int ni = 0; ni < 4; ni++) {
                const __nv_bfloat16* bp = Bs + (wn + ni*8)*AS_H + ka*16;
                bfr[ni][0] = *(const unsigned*)(bp + g*AS_H + tg*2);
                bfr[ni][1] = *(const unsigned*)(bp + g*AS_H + 8 + tg*2);
            }
            #pragma unroll
            for (int mi = 0; mi < 4; mi++)
                #pragma unroll
                for (int ni = 0; ni < 4; ni++)
                    asm volatile(
                        "mma.sync.aligned.m16n8k16.row.col.f32.bf16.bf16.f32 "
                        "{%0,%1,%2,%3},{%4,%5,%6,%7},{%8,%9},{%0,%1,%2,%3};"
                        : "+f"(acc[mi][ni][0]), "+f"(acc[mi][ni][1]),
                          "+f"(acc[mi][ni][2]), "+f"(acc[mi][ni][3])
                        : "r"(afr[mi][0]), "r"(afr[mi][1]), "r"(afr[mi][2]), "r"(afr[mi][3]),
                          "r"(bfr[ni][0]), "r"(bfr[ni][1]));
        }
        __syncthreads();
    }
    // epilogue: c0,c1 = row g; c2,c3 = row g+8
    #pragma unroll
    for (int mi = 0; mi < 4; mi++) {
        #pragma unroll
        for (int hh = 0; hh < 2; hh++) {
            int m = bm + wm + mi*16 + g + hh*8;
            if (m >= M) continue;
            #pragma unroll
            for (int ni = 0; ni < 4; ni++) {
                int n = bn + wn + ni*8 + tg*2;
                #pragma unroll
                for (int e = 0; e < 2; e++) {
                    int nn = n + e;
                    if (nn >= N) continue;
                    float v = acc[mi][ni][hh*2 + e];
                    if (bias) v += bias[nn];
                    if (addC) v += addC[(size_t)m * N + nn];
                    if (act == 1) v = tanhf(v);
                    C[(size_t)m * N + nn] = v;
                }
            }
        }
    }
}

// ---------------- fp32 SIMT GEMM (small cases: ANGI) ------------------------
__global__ void gemm_kernel(const float* __restrict__ A, const float* __restrict__ B,
                            const float* __restrict__ bias, float* __restrict__ C,
                            int M, int N, int K)
{
    const int BM = 128, BN = 128, BK = 16;
    __shared__ __align__(16) float As[BK][BM];
    __shared__ __align__(16) float Bs[BK][BN];
    int bm = blockIdx.y * BM, bn = blockIdx.x * BN;
    int tid = threadIdx.x;
    int tx = tid & 15, ty = tid >> 4;
    int lr = tid >> 1;
    int lk = (tid & 1) * 4;

    float acc[8][8];
    #pragma unroll
    for (int i = 0; i < 8; i++)
        #pragma unroll
        for (int j = 0; j < 8; j++) acc[i][j] = 0.f;

    for (int k0 = 0; k0 < K; k0 += BK) {
        {
            int m = bm + lr;
            float4 v0 = make_float4(0.f,0.f,0.f,0.f), v1 = v0;
            if (m < M) {
                const float* ap = A + (size_t)m * K + k0;
                v0 = *(const float4*)(ap + lk);
                v1 = *(const float4*)(ap + lk + 8);
            }
            As[lk+0][lr]=v0.x; As[lk+1][lr]=v0.y; As[lk+2][lr]=v0.z; As[lk+3][lr]=v0.w;
            As[lk+8][lr]=v1.x; As[lk+9][lr]=v1.y; As[lk+10][lr]=v1.z; As[lk+11][lr]=v1.w;
        }
        {
            int n = bn + lr;
            float4 v0 = make_float4(0.f,0.f,0.f,0.f), v1 = v0;
            if (n < N) {
                const float* bp = B + (size_t)n * K + k0;
                v0 = *(const float4*)(bp + lk);
                v1 = *(const float4*)(bp + lk + 8);
            }
            Bs[lk+0][lr]=v0.x; Bs[lk+1][lr]=v0.y; Bs[lk+2][lr]=v0.z; Bs[lk+3][lr]=v0.w;
            Bs[lk+8][lr]=v1.x; Bs[lk+9][lr]=v1.y; Bs[lk+10][lr]=v1.z; Bs[lk+11][lr]=v1.w;
        }
        __syncthreads();
        #pragma unroll
        for (int k = 0; k < BK; k++) {
            float a[8], b[8];
            *(float4*)&a[0] = *(const float4*)&As[k][ty*8];
            *(float4*)&a[4] = *(const float4*)&As[k][ty*8 + 4];
            *(float4*)&b[0] = *(const float4*)&Bs[k][tx*8];
            *(float4*)&b[4] = *(const float4*)&Bs[k][tx*8 + 4];
            #pragma unroll
            for (int i = 0; i < 8; i++)
                #pragma unroll
                for (int j = 0; j < 8; j++)
                    acc[i][j] = fmaf(a[i], b[j], acc[i][j]);
        }
        __syncthreads();
    }
    #pragma unroll
    for (int i = 0; i < 8; i++) {
        int m = bm + ty*8 + i;
        if (m >= M) continue;
        #pragma unroll
        for (int j = 0; j < 8; j++) {
            int n = bn + tx*8 + j;
            if (n >= N) continue;
            float v = acc[i][j];
            if (bias) v += bias[n];
            C[(size_t)m * N + n] = v;
        }
    }
}

// ---------------- merged weight-stationary multi-step GRU -------------------
// blocks [0, nb_f): fact GRU (PROJ gathered by tokens). blocks [nb_f, nb_f+nb_q):
// question GRU (dense QGI rows). T = 32 for both.
__global__ __launch_bounds__(256)
void gru_merged_kernel(const float* __restrict__ proj, const int* __restrict__ facts,
                       const float* __restrict__ igWhh, const float* __restrict__ igbhh,
                       const int* __restrict__ flen, float* __restrict__ encf,
                       const float* __restrict__ qgi, const float* __restrict__ qgWhh,
                       const float* __restrict__ qgbhh, const int* __restrict__ qlen,
                       float* __restrict__ qvec)
{
    extern __shared__ float sm[];
    float* WT   = sm;
    float* hsh  = WT  + 128*WT_STRIDE;
    float* gish = hsh + 16*H_STRIDE;
    __shared__ int len_sh[16];

    const int nb_f = NSEQF/16;
    bool isq = (blockIdx.x >= nb_f);
    const float* gi_tab   = isq ? qgi   : proj;
    const int*   tokens   = isq ? (const int*)0 : facts;
    const float* Whh      = isq ? qgWhh : igWhh;
    const float* bhh      = isq ? qgbhh : igbhh;
    const int*   lens     = isq ? qlen  : flen;
    float*       encout   = isq ? qvec  : encf;
    int base = (isq ? (blockIdx.x - nb_f) : blockIdx.x) * 16;
    const int T = 32;

    int tid = threadIdx.x;

    for (int idx = tid; idx < 384*32; idx += 256) {
        int g  = idx % 384;
        int k4 = idx / 384;
        float4 v = *(const float4*)(Whh + (size_t)g*HD + k4*4);
        WT[(k4*4+0)*WT_STRIDE + g] = v.x;
        WT[(k4*4+1)*WT_STRIDE + g] = v.y;
        WT[(k4*4+2)*WT_STRIDE + g] = v.z;
        WT[(k4*4+3)*WT_STRIDE + g] = v.w;
    }
    for (int i = tid; i < 16*H_STRIDE; i += 256) hsh[i] = 0.f;
    if (tid < 16) len_sh[tid] = lens[base + tid];
    __syncthreads();

    int jgrp = tid >> 3;
    int sgrp = tid & 7;
    int j0 = jgrp * 4;
    int s0 = sgrp * 2;

    float br[4], bz[4], bn_[4];
    #pragma unroll
    for (int i = 0; i < 4; i++) {
        br[i]  = bhh[j0 + i];
        bz[i]  = bhh[HD + j0 + i];
        bn_[i] = bhh[2*HD + j0 + i];
    }

    for (int t = 0; t < T; t++) {
        for (int i = tid; i < 16*96; i += 256) {
            int s = i / 96, c4 = i % 96;
            size_t srow;
            if (tokens) {
                int tok = tokens[(size_t)(base + s) * T + t];
                srow = (size_t)tok * G3;
            } else {
                srow = (size_t)((base + s) * T + t) * G3;
            }
            *(float4*)(gish + s*GI_STRIDE + c4*4) =
                *(const float4*)(gi_tab + srow + c4*4);
        }

        float ar00=0.f,ar01=0.f,ar10=0.f,ar11=0.f,ar20=0.f,ar21=0.f,ar30=0.f,ar31=0.f;
        float az00=0.f,az01=0.f,az10=0.f,az11=0.f,az20=0.f,az21=0.f,az30=0.f,az31=0.f;
        float an00=0.f,an01=0.f,an10=0.f,an11=0.f,an20=0.f,an21=0.f,an30=0.f,an31=0.f;
        const float* hp0 = hsh + s0*H_STRIDE;
        const float* hp1 = hsh + (s0+1)*H_STRIDE;
        #pragma unroll 4
        for (int k = 0; k < HD; k++) {
            const float* wrow = WT + k*WT_STRIDE;
            float4 wr = *(const float4*)(wrow + j0);
            float4 wz = *(const float4*)(wrow + HD + j0);
            float4 wn = *(const float4*)(wrow + 2*HD + j0);
            float h0 = hp0[k], h1 = hp1[k];
            ar00 = fmaf(wr.x, h0, ar00); ar01 = fmaf(wr.x, h1, ar01);
            ar10 = fmaf(wr.y, h0, ar10); ar11 = fmaf(wr.y, h1, ar11);
            ar20 = fmaf(wr.z, h0, ar20); ar21 = fmaf(wr.z, h1, ar21);
            ar30 = fmaf(wr.w, h0, ar30); ar31 = fmaf(wr.w, h1, ar31);
            az00 = fmaf(wz.x, h0, az00); az01 = fmaf(wz.x, h1, az01);
            az10 = fmaf(wz.y, h0, az10); az11 = fmaf(wz.y, h1, az11);
            az20 = fmaf(wz.z, h0, az20); az21 = fmaf(wz.z, h1, az21);
            az30 = fmaf(wz.w, h0, az30); az31 = fmaf(wz.w, h1, az31);
            an00 = fmaf(wn.x, h0, an00); an01 = fmaf(wn.x, h1, an01);
            an10 = fmaf(wn.y, h0, an10); an11 = fmaf(wn.y, h1, an11);
            an20 = fmaf(wn.z, h0, an20); an21 = fmaf(wn.z, h1, an21);
            an30 = fmaf(wn.w, h0, an30); an31 = fmaf(wn.w, h1, an31);
        }
        __syncthreads();

        float accr[4][2] = {{ar00,ar01},{ar10,ar11},{ar20,ar21},{ar30,ar31}};
        float accz[4][2] = {{az00,az01},{az10,az11},{az20,az21},{az30,az31}};
        float accn[4][2] = {{an00,an01},{an10,an11},{an20,an21},{an30,an31}};
        #pragma unroll
        for (int si = 0; si < 2; si++) {
            int s = s0 + si;
            float* hrow = hsh + s*H_STRIDE;
            const float* girow = gish + s*GI_STRIDE;
            int L = len_sh[s];
            int tlast = (L > 0) ? (L - 1) : 0;
            #pragma unroll
            for (int ji = 0; ji < 4; ji++) {
                int j = j0 + ji;
                float r = sigf(girow[j]        + accr[ji][si] + br[ji]);
                float z = sigf(girow[HD + j]   + accz[ji][si] + bz[ji]);
                float n = tanhf(girow[2*HD + j] + r * (accn[ji][si] + bn_[ji]));
                float hold = hrow[j];
                float hnew = (1.f - z) * n + z * hold;
                hrow[j] = hnew;
                if (t == tlast) encout[(size_t)(base + s) * HD + j] = hnew;
            }
        }
        __syncthreads();
    }
}

// ---------------- setup: memory init + yq build ----------------------------
__global__ void setup_kernel(const float* __restrict__ embed, const float* __restrict__ qvec,
                             float* __restrict__ mem, float* __restrict__ yq)
{
    int idx = blockIdx.x * blockDim.x + threadIdx.x;
    if (idx >= BATCH * HD) return;
    int b = idx / HD, j = idx % HD;
    float qv = qvec[idx];
    mem[idx] = qv;
    yq[b*2*HD + j]      = embed[2*HD + j];
    yq[b*2*HD + HD + j] = qv;
}

// ---------------- gate-path preprocessing (bf16 outputs) --------------------
__global__ void repack_w1_kernel(const float* __restrict__ W1,
                                 __nv_bfloat16* __restrict__ W1q,
                                 __nv_bfloat16* __restrict__ W1m)
{
    int idx = blockIdx.x * blockDim.x + threadIdx.x;
    if (idx >= HD * 2*HD) return;
    int o = idx >> 8, c = idx & 255;
    int cq = (c < HD) ? c : (2*HD + (c - HD));
    int cm = (c < HD) ? (HD + c) : (3*HD + (c - HD));
    W1q[idx] = __float2bfloat16(W1[o*4*HD + cq]);
    W1m[idx] = __float2bfloat16(W1[o*4*HD + cm]);
}

__global__ void buildzq_kernel(const float* __restrict__ encf, const float* __restrict__ q,
                               __nv_bfloat16* __restrict__ zq)
{
    int idx = blockIdx.x * blockDim.x + threadIdx.x;
    if (idx >= NSEQF * 2*HD) return;
    int row = idx >> 8, c = idx & 255, j = c & (HD-1), b = row / TCC;
    float f  = encf[row*HD + j];
    float qv = q[b*HD + j];
    zq[idx] = __float2bfloat16((c < HD) ? f * qv : fabsf(f - qv));
}

__global__ void buildzm_kernel(const float* __restrict__ encf, const float* __restrict__ mem,
                               __nv_bfloat16* __restrict__ zm)
{
    int idx = blockIdx.x * blockDim.x + threadIdx.x;
    if (idx >= NSEQF * 2*HD) return;
    int row = idx >> 8, c = idx & 255, j = c & (HD-1), b = row / TCC;
    float f  = encf[row*HD + j];
    float mv = mem[b*HD + j];
    zm[idx] = __float2bfloat16((c < HD) ? f * mv : fabsf(f - mv));
}

// ---------------- gate reduction -------------------------------------------
__global__ void gate_kernel(const float* __restrict__ U, const float* __restrict__ W2,
                            const float* __restrict__ b2, float* __restrict__ G)
{
    int warp = threadIdx.x >> 5, lane = threadIdx.x & 31;
    int row = blockIdx.x * (blockDim.x >> 5) + warp;
    if (row >= NSEQF) return;
    float s = 0.f;
    #pragma unroll
    for (int j = lane; j < HD; j += 32) s += U[(size_t)row*HD + j] * W2[j];
    #pragma unroll
    for (int o = 16; o; o >>= 1) s += __shfl_xor_sync(0xffffffffu, s, o);
    if (lane == 0) G[row] = sigf(s + b2[0]);
}

// ---------------- episode scan + memory GRU --------------------------------
__global__ void episode_kernel(const float* __restrict__ atgi, const float* __restrict__ gate,
                               const float* __restrict__ Whh, const float* __restrict__ bhh,
                               const float* __restrict__ meWih, const float* __restrict__ meWhh,
                               const float* __restrict__ mebih, const float* __restrict__ mebhh,
                               float* __restrict__ mem)
{
    __shared__ __align__(16) float h_sh[HD];
    __shared__ __align__(16) float msh[HD];
    __shared__ float rr[HD], zz[HD], gin[HD], ghn[HD];
    int b = blockIdx.x, g = threadIdx.x;
    int j = g & (HD - 1);
    if (g < HD) h_sh[g] = 0.f;
    __syncthreads();
    float bh = bhh[g];
    const float4* wr = (const float4*)(Whh + g * HD);

    for (int tc = 0; tc < TCC; tc++) {
        float gi = atgi[(size_t)(b*TCC + tc) * G3 + g];
        float gh = bh;
        #pragma unroll 8
        for (int kc = 0; kc < HD/4; kc++) {
            float4 w = __ldg(&wr[kc]);
            float4 h4 = *(const float4*)&h_sh[kc*4];
            gh = fmaf(w.x, h4.x, gh); gh = fmaf(w.y, h4.y, gh);
            gh = fmaf(w.z, h4.z, gh); gh = fmaf(w.w, h4.w, gh);
        }
        float v = gi + gh;
        if      (g < HD)   rr[j] = sigf(v);
        else if (g < 2*HD) zz[j] = sigf(v);
        else { gin[j] = gi; ghn[j] = gh; }
        __syncthreads();
        if (g < HD) {
            float r = rr[g], z = zz[g];
            float n = tanhf(gin[g] + r * ghn[g]);
            float h2 = (1.f - z) * n + z * h_sh[g];
            float gd = gate[b*TCC + tc];
            h_sh[g] = gd * h2 + (1.f - gd) * h_sh[g];
        }
        __syncthreads();
    }
    if (g < HD) msh[g] = mem[b*HD + g];
    __syncthreads();
    {
        float gi = mebih[g], gh = mebhh[g];
        const float4* wi = (const float4*)(meWih + g * HD);
        const float4* wh = (const float4*)(meWhh + g * HD);
        #pragma unroll 8
        for (int kc = 0; kc < HD/4; kc++) {
            float4 a = __ldg(&wi[kc]);
            float4 e4 = *(const float4*)&h_sh[kc*4];
            gi = fmaf(a.x, e4.x, gi); gi = fmaf(a.y, e4.y, gi);
            gi = fmaf(a.z, e4.z, gi); gi = fmaf(a.w, e4.w, gi);
            float4 c = __ldg(&wh[kc]);
            float4 m4 = *(const float4*)&msh[kc*4];
            gh = fmaf(c.x, m4.x, gh); gh = fmaf(c.y, m4.y, gh);
            gh = fmaf(c.z, m4.z, gh); gh = fmaf(c.w, m4.w, gh);
        }
        float v = gi + gh;
        if      (g < HD)   rr[j] = sigf(v);
        else if (g < 2*HD) zz[j] = sigf(v);
        else { gin[j] = gi; ghn[j] = gh; }
    }
    __syncthreads();
    if (g < HD) {
        float r = rr[g], z = zz[g];
        float n = tanhf(gin[g] + r * ghn[g]);
        mem[b*HD + g] = (1.f - z) * n + z * msh[g];
    }
}

// ---------------- decoder scan ---------------------------------------------
__global__ void decoder_kernel(const float* __restrict__ angi, const float* __restrict__ Whh,
                               const float* __restrict__ bhh, const float* __restrict__ mem,
                               float* __restrict__ hdec, int Tdec)
{
    __shared__ __align__(16) float h_sh[HD];
    __shared__ float rr[HD], zz[HD], gin[HD], ghn[HD];
    int b = blockIdx.x, g = threadIdx.x;
    int j = g & (HD - 1);
    if (g < HD) h_sh[g] = mem[b*HD + g];
    __syncthreads();
    float gi = angi[(size_t)b * G3 + g];
    float bh = bhh[g];
    const float4* wr = (const float4*)(Whh + g * HD);

    for (int t = 0; t < Tdec; t++) {
        float gh = bh;
        #pragma unroll 8
        for (int kc = 0; kc < HD/4; kc++) {
            float4 w = __ldg(&wr[kc]);
            float4 h4 = *(const float4*)&h_sh[kc*4];
            gh = fmaf(w.x, h4.x, gh); gh = fmaf(w.y, h4.y, gh);
            gh = fmaf(w.z, h4.z, gh); gh = fmaf(w.w, h4.w, gh);
        }
        float v = gi + gh;
        if      (g < HD)   rr[j] = sigf(v);
        else if (g < 2*HD) zz[j] = sigf(v);
        else { gin[j] = gi; ghn[j] = gh; }
        __syncthreads();
        if (g < HD) {
            float r = rr[g], z = zz[g];
            float n = tanhf(gin[g] + r * ghn[g]);
            float hn = (1.f - z) * n + z * h_sh[g];
            h_sh[g] = hn;
            hdec[(size_t)(b*Tdec + t) * HD + g] = hn;
        }
        __syncthreads();
    }
}

// ---------------- fused log-softmax (lse + subtract in one kernel) ----------
__global__ void lsesub_kernel(float* __restrict__ out, int V)
{
    __shared__ float sm[512], ss[512];
    __shared__ float lse_sh;
    int row = blockIdx.x, tid = threadIdx.x;
    float* x = out + (size_t)row * V;
    float m = -1e30f, s = 0.f;
    for (int i = tid; i < V; i += blockDim.x) {
        float v = x[i];
        if (v > m) { s = s * expf(m - v) + 1.f; m = v; }
        else       { s += expf(v - m); }
    }
    sm[tid] = m; ss[tid] = s;
    __syncthreads();
    for (int o = 256; o; o >>= 1) {
        if (tid < o) {
            float m2 = sm[tid + o], s2 = ss[tid + o];
            float M = fmaxf(sm[tid], m2);
            ss[tid] = ss[tid] * expf(sm[tid] - M) + s2 * expf(m2 - M);
            sm[tid] = M;
        }
        __syncthreads();
    }
    if (tid == 0) lse_sh = sm[0] + logf(ss[0]);
    __syncthreads();
    float L = lse_sh;
    for (int i = tid; i < V; i += blockDim.x) x[i] -= L;
}

// ---------------- host orchestration ---------------------------------------
extern "C" void kernel_launch(void* const* d_in, const int* in_sizes, int n_in,
                              void* d_out, int out_size)
{
    const int*   facts     = (const int*)  d_in[0];
    const int*   fmask     = (const int*)  d_in[1];
    const int*   questions = (const int*)  d_in[2];
    const int*   qmask     = (const int*)  d_in[3];
    const float* embed  = (const float*)d_in[5];
    const float* igWih  = (const float*)d_in[6],  *igWhh = (const float*)d_in[7];
    const float* igbih  = (const float*)d_in[8],  *igbhh = (const float*)d_in[9];
    const float* qgWih  = (const float*)d_in[10], *qgWhh = (const float*)d_in[11];
    const float* qgbih  = (const float*)d_in[12], *qgbhh = (const float*)d_in[13];
    const float* atWih  = (const float*)d_in[14], *atWhh = (const float*)d_in[15];
    const float* atbih  = (const float*)d_in[16], *atbhh = (const float*)d_in[17];
    const float* meWih  = (const float*)d_in[18], *meWhh = (const float*)d_in[19];
    const float* mebih  = (const float*)d_in[20], *mebhh = (const float*)d_in[21];
    const float* anWih  = (const float*)d_in[22], *anWhh = (const float*)d_in[23];
    const float* anbih  = (const float*)d_in[24], *anbhh = (const float*)d_in[25];
    const float* gateW1 = (const float*)d_in[26], *gateb1 = (const float*)d_in[27];
    const float* gateW2 = (const float*)d_in[28], *gateb2 = (const float*)d_in[29];
    const float* fcW    = (const float*)d_in[30], *fcb    = (const float*)d_in[31];
    float* out = (float*)d_out;

    int Tdec = out_size / (BATCH * VOCAB);
    if (Tdec < 1) Tdec = 1;
    if (Tdec > 32) Tdec = 32;

    float *proj, *qgi, *encf, *qvec, *memb, *yq, *atgi, *angi, *uq, *ub, *gb, *hdec;
    int *flen, *qlen;
    __nv_bfloat16 *emb16, *igw16, *qgw16, *atw16, *fcw16, *encf16, *hdec16;
    __nv_bfloat16 *zq16, *zm16, *w1q16, *w1m16;
    cudaGetSymbolAddress((void**)&proj, PROJ);
    cudaGetSymbolAddress((void**)&qgi,  QGI);
    cudaGetSymbolAddress((void**)&encf, ENCF);
    cudaGetSymbolAddress((void**)&qvec, QVEC);
    cudaGetSymbolAddress((void**)&memb, MEMB);
    cudaGetSymbolAddress((void**)&yq,   YQB);
    cudaGetSymbolAddress((void**)&atgi, ATGI);
    cudaGetSymbolAddress((void**)&angi, ANGI);
    cudaGetSymbolAddress((void**)&uq,   UQB);
    cudaGetSymbolAddress((void**)&ub,   UB);
    cudaGetSymbolAddress((void**)&gb,   GBUF);
    cudaGetSymbolAddress((void**)&hdec, HDEC);
    cudaGetSymbolAddress((void**)&flen, FLENB);
    cudaGetSymbolAddress((void**)&qlen, QLENB);
    cudaGetSymbolAddress((void**)&emb16,  EMB16);
    cudaGetSymbolAddress((void**)&igw16,  IGW16);
    cudaGetSymbolAddress((void**)&qgw16,  QGW16);
    cudaGetSymbolAddress((void**)&atw16,  ATW16);
    cudaGetSymbolAddress((void**)&fcw16,  FCW16);
    cudaGetSymbolAddress((void**)&encf16, ENCF16);
    cudaGetSymbolAddress((void**)&hdec16, HDEC16);
    cudaGetSymbolAddress((void**)&zq16,   ZQ16);
    cudaGetSymbolAddress((void**)&zm16,   ZM16);
    cudaGetSymbolAddress((void**)&w1q16,  W1Q16);
    cudaGetSymbolAddress((void**)&w1m16,  W1M16);

    cudaFuncSetAttribute(gru_merged_kernel,
                         cudaFuncAttributeMaxDynamicSharedMemorySize, GRU_SMEM_BYTES);

    // 1) lengths + weight conversions
    len_kernel<<<(NSEQF + BATCH + 255) / 256, 256>>>(fmask, qmask, flen, qlen);
    cvt_kernel<<<(VOCAB*HD/4 + 255)/256, 256>>>(embed, emb16, VOCAB*HD/4);
    cvt_kernel<<<(G3*HD/4 + 255)/256, 256>>>(igWih, igw16, G3*HD/4);
    cvt_kernel<<<(G3*HD/4 + 255)/256, 256>>>(qgWih, qgw16, G3*HD/4);
    cvt_kernel<<<(G3*HD/4 + 255)/256, 256>>>(atWih, atw16, G3*HD/4);
    cvt_kernel<<<(VOCAB*HD/4 + 255)/256, 256>>>(fcW, fcw16, VOCAB*HD/4);
    repack_w1_kernel<<<(HD*2*HD + 255)/256, 256>>>(gateW1, w1q16, w1m16);

    // 2) PROJ = embed @ ig_Wih^T + ig_bih (tensor cores)
    {
        dim3 g((G3 + 127)/128, (VOCAB + 127)/128);
        bgemm_kernel<<<g, 256>>>(emb16, nullptr, igw16, igbih, nullptr, proj, VOCAB, G3, HD, 0);
    }
    // 3) QGI = embed[questions] @ qg_Wih^T + qg_bih
    {
        dim3 g((G3 + 127)/128, (BATCH*TQ + 127)/128);
        bgemm_kernel<<<g, 256>>>(emb16, questions, qgw16, qgbih, nullptr, qgi, BATCH*TQ, G3, HD, 0);
    }
    // 4) fact + question recurrences (merged single launch)
    gru_merged_kernel<<<NSEQF/16 + BATCH/16, 256, GRU_SMEM_BYTES>>>(
        proj, facts, igWhh, igbhh, flen, encf,
        qgi, qgWhh, qgbhh, qlen, qvec);

    // 5) memory = q; yq = [embed[2], q]
    setup_kernel<<<(BATCH*HD + 255)/256, 256>>>(embed, qvec, memb, yq);
    cvt_kernel<<<(NSEQF*HD/4 + 255)/256, 256>>>(encf, encf16, NSEQF*HD/4);

    // 6) ATGI = enc_f @ at_Wih^T + at_bih
    {
        dim3 g((G3 + 127)/128, (NSEQF + 127)/128);
        bgemm_kernel<<<g, 256>>>(encf16, nullptr, atw16, atbih, nullptr, atgi, NSEQF, G3, HD, 0);
    }
    // 7) ANGI = yq @ an_Wih^T + an_bih (small, fp32 SIMT)
    {
        dim3 g((G3 + 127)/128, 1);
        gemm_kernel<<<g, 256>>>(yq, anWih, anbih, angi, BATCH, G3, 2*HD);
    }

    // 8) gate path: episode-invariant half once
    buildzq_kernel<<<(NSEQF*2*HD + 255)/256, 256>>>(encf, qvec, zq16);
    {
        dim3 g(1, (NSEQF + 127)/128);
        bgemm_kernel<<<g, 256>>>(zq16, nullptr, w1q16, nullptr, nullptr, uq, NSEQF, HD, 2*HD, 0);
    }

    // 9) episodic memory: 3 episodes
    for (int ep = 0; ep < EPISODES; ep++) {
        buildzm_kernel<<<(NSEQF*2*HD + 255)/256, 256>>>(encf, memb, zm16);
        {
            dim3 g(1, (NSEQF + 127)/128);
            bgemm_kernel<<<g, 256>>>(zm16, nullptr, w1m16, gateb1, uq, ub, NSEQF, HD, 2*HD, 1);
        }
        gate_kernel<<<NSEQF/8, 256>>>(ub, gateW2, gateb2, gb);
        episode_kernel<<<BATCH, G3>>>(atgi, gb, atWhh, atbhh,
                                      meWih, meWhh, mebih, mebhh, memb);
    }

    // 10) decoder hidden states + convert
    decoder_kernel<<<BATCH, G3>>>(angi, anWhh, anbhh, memb, hdec, Tdec);
    cvt_kernel<<<(BATCH*Tdec*HD/4 + 255)/256, 256>>>(hdec, hdec16, BATCH*Tdec*HD/4);

    // 11) logits into d_out (tensor cores) + fused log-softmax
    {
        dim3 g((VOCAB + 127)/128, (BATCH*Tdec + 127)/128);
        bgemm_kernel<<<g, 256>>>(hdec16, nullptr, fcw16, fcb, nullptr, out, BATCH*Tdec, VOCAB, HD, 0);
    }
    lsesub_kernel<<<BATCH*Tdec, 512>>>(out, VOCAB);
}

// round 9
// speedup vs baseline: 2.2062x; 1.2004x over previous
#include <cuda_runtime.h>
#include <cuda_bf16.h>
#include <math.h>

#define HD     128
#define VOCAB  50000
#define BATCH  128
#define TCC    50
#define TI     32
#define TQ     32
#define NSEQF  (BATCH*TCC)     /* 6400 */
#define G3     (3*HD)          /* 384 */
#define EPISODES 3

// bgemm smem stride (halves): 72 halves = 144B -> conflict-free
#define AS_H 72

// tensor-GRU smem layout
#define WB_STRIDE  136   /* bf16 stride for W and h operand tiles */
#define GH_STRIDE  392   /* fp32 gh stride */
#define GIF_STRIDE 388   /* fp32 gi stride */
#define GRUT_SMEM_BYTES (16*GIF_STRIDE*4 + 16*GH_STRIDE*4 + 16*129*4 + 384*4 \
                         + 384*WB_STRIDE*2 + 16*WB_STRIDE*2)

// ---------------- static scratch -----------------------------------------
__device__ __align__(256) float PROJ [VOCAB*G3];
__device__ __align__(256) float QGI  [BATCH*TQ*G3];
__device__ __align__(256) float ENCF [NSEQF*HD];
__device__ __align__(256) float QVEC [BATCH*HD];
__device__ __align__(256) float MEMB [BATCH*HD];
__device__ __align__(256) float YQB  [BATCH*2*HD];
__device__ __align__(256) float ATGI [NSEQF*G3];
__device__ __align__(256) float ANGI [BATCH*G3];
__device__ __align__(256) float UQB  [NSEQF*HD];
__device__ __align__(256) float UB   [NSEQF*HD];
__device__ __align__(256) float GBUF [NSEQF];
__device__ __align__(256) int   FLENB[NSEQF];
__device__ __align__(256) int   QLENB[BATCH];
__device__ __align__(256) float HDEC [BATCH*32*HD];

// bf16 scratch
__device__ __align__(256) __nv_bfloat16 EMB16 [VOCAB*HD];
__device__ __align__(256) __nv_bfloat16 IGW16 [G3*HD];
__device__ __align__(256) __nv_bfloat16 QGW16 [G3*HD];
__device__ __align__(256) __nv_bfloat16 ATW16 [G3*HD];
__device__ __align__(256) __nv_bfloat16 FCW16 [VOCAB*HD];
__device__ __align__(256) __nv_bfloat16 ENCF16[NSEQF*HD];
__device__ __align__(256) __nv_bfloat16 HDEC16[BATCH*32*HD];
__device__ __align__(256) __nv_bfloat16 ZQ16  [NSEQF*2*HD];
__device__ __align__(256) __nv_bfloat16 ZM16  [NSEQF*2*HD];
__device__ __align__(256) __nv_bfloat16 W1Q16 [HD*2*HD];
__device__ __align__(256) __nv_bfloat16 W1M16 [HD*2*HD];

__device__ __forceinline__ float sigf(float x) { return 1.f / (1.f + expf(-x)); }

// ---------------- f32 -> bf16 convert --------------------------------------
__global__ void cvt_kernel(const float* __restrict__ src, __nv_bfloat16* __restrict__ dst, int n4)
{
    int i = blockIdx.x * blockDim.x + threadIdx.x;
    if (i >= n4) return;
    float4 v = *(const float4*)(src + i*4);
    __nv_bfloat16 o[4];
    o[0] = __float2bfloat16(v.x); o[1] = __float2bfloat16(v.y);
    o[2] = __float2bfloat16(v.z); o[3] = __float2bfloat16(v.w);
    *(uint2*)(dst + i*4) = *(uint2*)o;
}

// ---------------- sequence lengths ----------------------------------------
__global__ void len_kernel(const int* __restrict__ fmask, const int* __restrict__ qmask,
                           int* __restrict__ flen, int* __restrict__ qlen)
{
    int idx = blockIdx.x * blockDim.x + threadIdx.x;
    if (idx < NSEQF) {
        int c = 0;
        #pragma unroll
        for (int t = 0; t < TI; t++) c += (fmask[idx*TI + t] == 0);
        flen[idx] = c;
    } else if (idx < NSEQF + BATCH) {
        int q = idx - NSEQF;
        int c = 0;
        #pragma unroll
        for (int t = 0; t < TQ; t++) c += (qmask[q*TQ + t] == 0);
        qlen[q] = c;
    }
}

// ---------------- bf16 tensor-core GEMM: C = act(A@B^T + bias + addC) ------
__global__ __launch_bounds__(256)
void bgemm_kernel(const __nv_bfloat16* __restrict__ A, const int* __restrict__ gather,
                  const __nv_bfloat16* __restrict__ B, const float* __restrict__ bias,
                  const float* __restrict__ addC, float* __restrict__ C,
                  int M, int N, int K, int act)
{
    __shared__ __align__(16) __nv_bfloat16 As[128*AS_H];
    __shared__ __align__(16) __nv_bfloat16 Bs[128*AS_H];
    int bm = blockIdx.y * 128, bn = blockIdx.x * 128;
    int tid = threadIdx.x;
    int warp = tid >> 5, lane = tid & 31;
    int g = lane >> 2, tg = lane & 3;
    int wm = (warp >> 2) * 64, wn = (warp & 3) * 32;

    float acc[4][4][4];
    #pragma unroll
    for (int mi = 0; mi < 4; mi++)
        #pragma unroll
        for (int ni = 0; ni < 4; ni++)
            #pragma unroll
            for (int r = 0; r < 4; r++) acc[mi][ni][r] = 0.f;

    for (int k0 = 0; k0 < K; k0 += 32) {
        #pragma unroll
        for (int c = 0; c < 2; c++) {
            int chunk = tid + 256*c;
            int row = chunk >> 2, kc = chunk & 3;
            int m = bm + row;
            uint4 v = make_uint4(0,0,0,0);
            if (m < M) {
                int ar = gather ? gather[m] : m;
                v = *(const uint4*)(A + (size_t)ar * K + k0 + kc*8);
            }
            *(uint4*)(As + row*AS_H + kc*8) = v;
        }
        #pragma unroll
        for (int c = 0; c < 2; c++) {
            int chunk = tid + 256*c;
            int row = chunk >> 2, kc = chunk & 3;
            int n = bn + row;
            uint4 v = make_uint4(0,0,0,0);
            if (n < N) v = *(const uint4*)(B + (size_t)n * K + k0 + kc*8);
            *(uint4*)(Bs + row*AS_H + kc*8) = v;
        }
        __syncthreads();
        #pragma unroll
        for (int ka = 0; ka < 2; ka++) {
            unsigned afr[4][4], bfr[4][2];
            #pragma unroll
            for (int mi = 0; mi < 4; mi++) {
                const __nv_bfloat16* ap = As + (wm + mi*16)*AS_H + ka*16;
                afr[mi][0] = *(const unsigned*)(ap + g*AS_H + tg*2);
                afr[mi][1] = *(const unsigned*)(ap + (g+8)*AS_H + tg*2);
                afr[mi][2] = *(const unsigned*)(ap + g*AS_H + 8 + tg*2);
                afr[mi][3] = *(const unsigned*)(ap + (g+8)*AS_H + 8 + tg*2);
            }
            #pragma unroll
            for (int ni = 0; ni < 4; ni++) {
                const __nv_bfloat16* bp = Bs + (wn + ni*8)*AS_H + ka*16;
                bfr[ni][0] = *(const unsigned*)(bp + g*AS_H + tg*2);
                bfr[ni][1] = *(const unsigned*)(bp + g*AS_H + 8 + tg*2);
            }
            #pragma unroll
            for (int mi = 0; mi < 4; mi++)
                #pragma unroll
                for (int ni = 0; ni < 4; ni++)
                    asm volatile(
                        "mma.sync.aligned.m16n8k16.row.col.f32.bf16.bf16.f32 "
                        "{%0,%1,%2,%3},{%4,%5,%6,%7},{%8,%9},{%0,%1,%2,%3};"
                        : "+f"(acc[mi][ni][0]), "+f"(acc[mi][ni][1]),
                          "+f"(acc[mi][ni][2]), "+f"(acc[mi][ni][3])
                        : "r"(afr[mi][0]), "r"(afr[mi][1]), "r"(afr[mi][2]), "r"(afr[mi][3]),
                          "r"(bfr[ni][0]), "r"(bfr[ni][1]));
        }
        __syncthreads();
    }
    #pragma unroll
    for (int mi = 0; mi < 4; mi++) {
        #pragma unroll
        for (int hh = 0; hh < 2; hh++) {
            int m = bm + wm + mi*16 + g + hh*8;
            if (m >= M) continue;
            #pragma unroll
            for (int ni = 0; ni < 4; ni++) {
                int n = bn + wn + ni*8 + tg*2;
                #pragma unroll
                for (int e = 0; e < 2; e++) {
                    int nn = n + e;
                    if (nn >= N) continue;
                    float v = acc[mi][ni][hh*2 + e];
                    if (bias) v += bias[nn];
                    if (addC) v += addC[(size_t)m * N + nn];
                    if (act == 1) v = tanhf(v);
                    C[(size_t)m * N + nn] = v;
                }
            }
        }
    }
}

// ---------------- fp32 SIMT GEMM (small: ANGI) ------------------------------
__global__ void gemm_kernel(const float* __restrict__ A, const float* __restrict__ B,
                            const float* __restrict__ bias, float* __restrict__ C,
                            int M, int N, int K)
{
    const int BM = 128, BN = 128, BK = 16;
    __shared__ __align__(16) float As[BK][BM];
    __shared__ __align__(16) float Bs[BK][BN];
    int bm = blockIdx.y * BM, bn = blockIdx.x * BN;
    int tid = threadIdx.x;
    int tx = tid & 15, ty = tid >> 4;
    int lr = tid >> 1;
    int lk = (tid & 1) * 4;

    float acc[8][8];
    #pragma unroll
    for (int i = 0; i < 8; i++)
        #pragma unroll
        for (int j = 0; j < 8; j++) acc[i][j] = 0.f;

    for (int k0 = 0; k0 < K; k0 += BK) {
        {
            int m = bm + lr;
            float4 v0 = make_float4(0.f,0.f,0.f,0.f), v1 = v0;
            if (m < M) {
                const float* ap = A + (size_t)m * K + k0;
                v0 = *(const float4*)(ap + lk);
                v1 = *(const float4*)(ap + lk + 8);
            }
            As[lk+0][lr]=v0.x; As[lk+1][lr]=v0.y; As[lk+2][lr]=v0.z; As[lk+3][lr]=v0.w;
            As[lk+8][lr]=v1.x; As[lk+9][lr]=v1.y; As[lk+10][lr]=v1.z; As[lk+11][lr]=v1.w;
        }
        {
            int n = bn + lr;
            float4 v0 = make_float4(0.f,0.f,0.f,0.f), v1 = v0;
            if (n < N) {
                const float* bp = B + (size_t)n * K + k0;
                v0 = *(const float4*)(bp + lk);
                v1 = *(const float4*)(bp + lk + 8);
            }
            Bs[lk+0][lr]=v0.x; Bs[lk+1][lr]=v0.y; Bs[lk+2][lr]=v0.z; Bs[lk+3][lr]=v0.w;
            Bs[lk+8][lr]=v1.x; Bs[lk+9][lr]=v1.y; Bs[lk+10][lr]=v1.z; Bs[lk+11][lr]=v1.w;
        }
        __syncthreads();
        #pragma unroll
        for (int k = 0; k < BK; k++) {
            float a[8], b[8];
            *(float4*)&a[0] = *(const float4*)&As[k][ty*8];
            *(float4*)&a[4] = *(const float4*)&As[k][ty*8 + 4];
            *(float4*)&b[0] = *(const float4*)&Bs[k][tx*8];
            *(float4*)&b[4] = *(const float4*)&Bs[k][tx*8 + 4];
            #pragma unroll
            for (int i = 0; i < 8; i++)
                #pragma unroll
                for (int j = 0; j < 8; j++)
                    acc[i][j] = fmaf(a[i], b[j], acc[i][j]);
        }
        __syncthreads();
    }
    #pragma unroll
    for (int i = 0; i < 8; i++) {
        int m = bm + ty*8 + i;
        if (m >= M) continue;
        #pragma unroll
        for (int j = 0; j < 8; j++) {
            int n = bn + tx*8 + j;
            if (n >= N) continue;
            float v = acc[i][j];
            if (bias) v += bias[n];
            C[(size_t)m * N + n] = v;
        }
    }
}

// ---------------- tensor-core multi-step GRU --------------------------------
// 16 seqs/block, 256 threads (8 warps). Per step: gh[16x384] = h[16x128] @ Whh^T
// via mma.m16n8k16 (warp w covers n = 48w..48w+47), h kept fp32, bf16 operand copy.
// blocks [0, nb_f): fact GRU; blocks [nb_f, nb_f+8): question GRU. T = 32.
__global__ __launch_bounds__(256)
void gru_tc_kernel(const float* __restrict__ proj, const int* __restrict__ facts,
                   const float* __restrict__ igWhh, const float* __restrict__ igbhh,
                   const int* __restrict__ flen, float* __restrict__ encf,
                   const float* __restrict__ qgi, const float* __restrict__ qgWhh,
                   const float* __restrict__ qgbhh, const int* __restrict__ qlen,
                   float* __restrict__ qvec)
{
    extern __shared__ __align__(16) unsigned char smraw[];
    float* gif = (float*)smraw;                          // [16][GIF_STRIDE]
    float* ghf = gif + 16*GIF_STRIDE;                    // [16][GH_STRIDE]
    float* hfp = ghf + 16*GH_STRIDE;                     // [16][129]
    float* bsh = hfp + 16*129;                           // [384]
    __nv_bfloat16* Wsh = (__nv_bfloat16*)(bsh + 384);    // [384][WB_STRIDE]
    __nv_bfloat16* hb  = Wsh + 384*WB_STRIDE;            // [16][WB_STRIDE]
    __shared__ int len_sh[16];

    const int nb_f = NSEQF/16;
    bool isq = (blockIdx.x >= nb_f);
    const float* gi_tab = isq ? qgi   : proj;
    const int*   tokens = isq ? (const int*)0 : facts;
    const float* Whh    = isq ? qgWhh : igWhh;
    const float* bhh    = isq ? qgbhh : igbhh;
    const int*   lens   = isq ? qlen  : flen;
    float*       encout = isq ? qvec  : encf;
    int base = (isq ? (blockIdx.x - nb_f) : blockIdx.x) * 16;
    const int T = 32;

    int tid = threadIdx.x;
    int warp = tid >> 5, lane = tid & 31;
    int g = lane >> 2, tg = lane & 3;
    int wn = warp * 48;

    // stage Whh -> bf16 smem [n][k], stride WB_STRIDE
    for (int idx = tid; idx < 384*32; idx += 256) {
        int r = idx >> 5, c4 = idx & 31;
        float4 v = *(const float4*)(Whh + (size_t)r*HD + c4*4);
        __nv_bfloat16 o[4];
        o[0] = __float2bfloat16(v.x); o[1] = __float2bfloat16(v.y);
        o[2] = __float2bfloat16(v.z); o[3] = __float2bfloat16(v.w);
        *(uint2*)(Wsh + r*WB_STRIDE + c4*4) = *(uint2*)o;
    }
    for (int i = tid; i < 384; i += 256) bsh[i] = bhh[i];
    for (int i = tid; i < 16*129; i += 256) hfp[i] = 0.f;
    for (int i = tid; i < 16*WB_STRIDE; i += 256) hb[i] = __float2bfloat16(0.f);
    if (tid < 16) len_sh[tid] = lens[base + tid];
    __syncthreads();

    int ps = tid >> 4;            // pointwise: seq 0..15
    int pj = (tid & 15) * 8;      // 8 consecutive j per thread

    for (int t = 0; t < T; t++) {
        // stage gi (fp32) for all 16 seqs
        for (int i = tid; i < 16*96; i += 256) {
            int s = i / 96, c4 = i % 96;
            size_t srow;
            if (tokens) {
                int tok = tokens[(size_t)(base + s) * T + t];
                srow = (size_t)tok * G3;
            } else {
                srow = (size_t)((base + s) * T + t) * G3;
            }
            *(float4*)(gif + s*GIF_STRIDE + c4*4) =
                *(const float4*)(gi_tab + srow + c4*4);
        }

        // gh = h @ Whh^T via tensor cores (reads hb from previous step)
        float acc[6][4];
        #pragma unroll
        for (int ni = 0; ni < 6; ni++)
            #pragma unroll
            for (int r = 0; r < 4; r++) acc[ni][r] = 0.f;

        #pragma unroll
        for (int ka = 0; ka < 8; ka++) {
            const __nv_bfloat16* ap = hb + ka*16;
            unsigned a0 = *(const unsigned*)(ap + g*WB_STRIDE + tg*2);
            unsigned a1 = *(const unsigned*)(ap + (g+8)*WB_STRIDE + tg*2);
            unsigned a2 = *(const unsigned*)(ap + g*WB_STRIDE + 8 + tg*2);
            unsigned a3 = *(const unsigned*)(ap + (g+8)*WB_STRIDE + 8 + tg*2);
            #pragma unroll
            for (int ni = 0; ni < 6; ni++) {
                const __nv_bfloat16* bp = Wsh + (wn + ni*8 + g)*WB_STRIDE + ka*16 + tg*2;
                unsigned b0 = *(const unsigned*)bp;
                unsigned b1 = *(const unsigned*)(bp + 8);
                asm volatile(
                    "mma.sync.aligned.m16n8k16.row.col.f32.bf16.bf16.f32 "
                    "{%0,%1,%2,%3},{%4,%5,%6,%7},{%8,%9},{%0,%1,%2,%3};"
                    : "+f"(acc[ni][0]), "+f"(acc[ni][1]),
                      "+f"(acc[ni][2]), "+f"(acc[ni][3])
                    : "r"(a0), "r"(a1), "r"(a2), "r"(a3), "r"(b0), "r"(b1));
            }
        }
        // write gh to smem
        #pragma unroll
        for (int ni = 0; ni < 6; ni++) {
            int n = wn + ni*8 + tg*2;
            ghf[g*GH_STRIDE + n]       = acc[ni][0];
            ghf[g*GH_STRIDE + n + 1]   = acc[ni][1];
            ghf[(g+8)*GH_STRIDE + n]     = acc[ni][2];
            ghf[(g+8)*GH_STRIDE + n + 1] = acc[ni][3];
        }
        __syncthreads();

        // pointwise GRU update (fp32 master h)
        {
            int L = len_sh[ps];
            int tlast = (L > 0) ? (L - 1) : 0;
            const float* gi_s = gif + ps*GIF_STRIDE;
            const float* gh_s = ghf + ps*GH_STRIDE;
            float* hrow = hfp + ps*129;
            __nv_bfloat16* hbrow = hb + ps*WB_STRIDE;
            #pragma unroll
            for (int jj = 0; jj < 8; jj++) {
                int j = pj + jj;
                float r = sigf(gi_s[j]        + gh_s[j]        + bsh[j]);
                float z = sigf(gi_s[HD + j]   + gh_s[HD + j]   + bsh[HD + j]);
                float n = tanhf(gi_s[2*HD + j] + r * (gh_s[2*HD + j] + bsh[2*HD + j]));
                float hold = hrow[j];
                float hnew = (1.f - z) * n + z * hold;
                hrow[j] = hnew;
                hbrow[j] = __float2bfloat16(hnew);
                if (t == tlast) encout[(size_t)(base + ps) * HD + j] = hnew;
            }
        }
        __syncthreads();
    }
}

// ---------------- setup: memory init + yq build ----------------------------
__global__ void setup_kernel(const float* __restrict__ embed, const float* __restrict__ qvec,
                             float* __restrict__ mem, float* __restrict__ yq)
{
    int idx = blockIdx.x * blockDim.x + threadIdx.x;
    if (idx >= BATCH * HD) return;
    int b = idx / HD, j = idx % HD;
    float qv = qvec[idx];
    mem[idx] = qv;
    yq[b*2*HD + j]      = embed[2*HD + j];
    yq[b*2*HD + HD + j] = qv;
}

// ---------------- gate-path preprocessing ----------------------------------
__global__ void repack_w1_kernel(const float* __restrict__ W1,
                                 __nv_bfloat16* __restrict__ W1q,
                                 __nv_bfloat16* __restrict__ W1m)
{
    int idx = blockIdx.x * blockDim.x + threadIdx.x;
    if (idx >= HD * 2*HD) return;
    int o = idx >> 8, c = idx & 255;
    int cq = (c < HD) ? c : (2*HD + (c - HD));
    int cm = (c < HD) ? (HD + c) : (3*HD + (c - HD));
    W1q[idx] = __float2bfloat16(W1[o*4*HD + cq]);
    W1m[idx] = __float2bfloat16(W1[o*4*HD + cm]);
}

__global__ void buildzq_kernel(const float* __restrict__ encf, const float* __restrict__ q,
                               __nv_bfloat16* __restrict__ zq)
{
    int idx = blockIdx.x * blockDim.x + threadIdx.x;
    if (idx >= NSEQF * 2*HD) return;
    int row = idx >> 8, c = idx & 255, j = c & (HD-1), b = row / TCC;
    float f  = encf[row*HD + j];
    float qv = q[b*HD + j];
    zq[idx] = __float2bfloat16((c < HD) ? f * qv : fabsf(f - qv));
}

__global__ void buildzm_kernel(const float* __restrict__ encf, const float* __restrict__ mem,
                               __nv_bfloat16* __restrict__ zm)
{
    int idx = blockIdx.x * blockDim.x + threadIdx.x;
    if (idx >= NSEQF * 2*HD) return;
    int row = idx >> 8, c = idx & 255, j = c & (HD-1), b = row / TCC;
    float f  = encf[row*HD + j];
    float mv = mem[b*HD + j];
    zm[idx] = __float2bfloat16((c < HD) ? f * mv : fabsf(f - mv));
}

// ---------------- gate reduction -------------------------------------------
__global__ void gate_kernel(const float* __restrict__ U, const float* __restrict__ W2,
                            const float* __restrict__ b2, float* __restrict__ G)
{
    int warp = threadIdx.x >> 5, lane = threadIdx.x & 31;
    int row = blockIdx.x * (blockDim.x >> 5) + warp;
    if (row >= NSEQF) return;
    float s = 0.f;
    #pragma unroll
    for (int j = lane; j < HD; j += 32) s += U[(size_t)row*HD + j] * W2[j];
    #pragma unroll
    for (int o = 16; o; o >>= 1) s += __shfl_xor_sync(0xffffffffu, s, o);
    if (lane == 0) G[row] = sigf(s + b2[0]);
}

// ---------------- episode scan + memory GRU --------------------------------
__global__ void episode_kernel(const float* __restrict__ atgi, const float* __restrict__ gate,
                               const float* __restrict__ Whh, const float* __restrict__ bhh,
                               const float* __restrict__ meWih, const float* __restrict__ meWhh,
                               const float* __restrict__ mebih, const float* __restrict__ mebhh,
                               float* __restrict__ mem)
{
    __shared__ __align__(16) float h_sh[HD];
    __shared__ __align__(16) float msh[HD];
    __shared__ float rr[HD], zz[HD], gin[HD], ghn[HD];
    int b = blockIdx.x, g = threadIdx.x;
    int j = g & (HD - 1);
    if (g < HD) h_sh[g] = 0.f;
    __syncthreads();
    float bh = bhh[g];
    const float4* wr = (const float4*)(Whh + g * HD);

    for (int tc = 0; tc < TCC; tc++) {
        float gi = atgi[(size_t)(b*TCC + tc) * G3 + g];
        float gh = bh;
        #pragma unroll 8
        for (int kc = 0; kc < HD/4; kc++) {
            float4 w = __ldg(&wr[kc]);
            float4 h4 = *(const float4*)&h_sh[kc*4];
            gh = fmaf(w.x, h4.x, gh); gh = fmaf(w.y, h4.y, gh);
            gh = fmaf(w.z, h4.z, gh); gh = fmaf(w.w, h4.w, gh);
        }
        float v = gi + gh;
        if      (g < HD)   rr[j] = sigf(v);
        else if (g < 2*HD) zz[j] = sigf(v);
        else { gin[j] = gi; ghn[j] = gh; }
        __syncthreads();
        if (g < HD) {
            float r = rr[g], z = zz[g];
            float n = tanhf(gin[g] + r * ghn[g]);
            float h2 = (1.f - z) * n + z * h_sh[g];
            float gd = gate[b*TCC + tc];
            h_sh[g] = gd * h2 + (1.f - gd) * h_sh[g];
        }
        __syncthreads();
    }
    if (g < HD) msh[g] = mem[b*HD + g];
    __syncthreads();
    {
        float gi = mebih[g], gh = mebhh[g];
        const float4* wi = (const float4*)(meWih + g * HD);
        const float4* wh = (const float4*)(meWhh + g * HD);
        #pragma unroll 8
        for (int kc = 0; kc < HD/4; kc++) {
            float4 a = __ldg(&wi[kc]);
            float4 e4 = *(const float4*)&h_sh[kc*4];
            gi = fmaf(a.x, e4.x, gi); gi = fmaf(a.y, e4.y, gi);
            gi = fmaf(a.z, e4.z, gi); gi = fmaf(a.w, e4.w, gi);
            float4 c = __ldg(&wh[kc]);
            float4 m4 = *(const float4*)&msh[kc*4];
            gh = fmaf(c.x, m4.x, gh); gh = fmaf(c.y, m4.y, gh);
            gh = fmaf(c.z, m4.z, gh); gh = fmaf(c.w, m4.w, gh);
        }
        float v = gi + gh;
        if      (g < HD)   rr[j] = sigf(v);
        else if (g < 2*HD) zz[j] = sigf(v);
        else { gin[j] = gi; ghn[j] = gh; }
    }
    __syncthreads();
    if (g < HD) {
        float r = rr[g], z = zz[g];
        float n = tanhf(gin[g] + r * ghn[g]);
        mem[b*HD + g] = (1.f - z) * n + z * msh[g];
    }
}

// ---------------- decoder scan ---------------------------------------------
__global__ void decoder_kernel(const float* __restrict__ angi, const float* __restrict__ Whh,
                               const float* __restrict__ bhh, const float* __restrict__ mem,
                               float* __restrict__ hdec, int Tdec)
{
    __shared__ __align__(16) float h_sh[HD];
    __shared__ float rr[HD], zz[HD], gin[HD], ghn[HD];
    int b = blockIdx.x, g = threadIdx.x;
    int j = g & (HD - 1);
    if (g < HD) h_sh[g] = mem[b*HD + g];
    __syncthreads();
    float gi = angi[(size_t)b * G3 + g];
    float bh = bhh[g];
    const float4* wr = (const float4*)(Whh + g * HD);

    for (int t = 0; t < Tdec; t++) {
        float gh = bh;
        #pragma unroll 8
        for (int kc = 0; kc < HD/4; kc++) {
            float4 w = __ldg(&wr[kc]);
            float4 h4 = *(const float4*)&h_sh[kc*4];
            gh = fmaf(w.x, h4.x, gh); gh = fmaf(w.y, h4.y, gh);
            gh = fmaf(w.z, h4.z, gh); gh = fmaf(w.w, h4.w, gh);
        }
        float v = gi + gh;
        if      (g < HD)   rr[j] = sigf(v);
        else if (g < 2*HD) zz[j] = sigf(v);
        else { gin[j] = gi; ghn[j] = gh; }
        __syncthreads();
        if (g < HD) {
            float r = rr[g], z = zz[g];
            float n = tanhf(gin[g] + r * ghn[g]);
            float hn = (1.f - z) * n + z * h_sh[g];
            h_sh[g] = hn;
            hdec[(size_t)(b*Tdec + t) * HD + g] = hn;
        }
        __syncthreads();
    }
}

// ---------------- fused log-softmax ----------------------------------------
__global__ void lsesub_kernel(float* __restrict__ out, int V)
{
    __shared__ float sm[512], ss[512];
    __shared__ float lse_sh;
    int row = blockIdx.x, tid = threadIdx.x;
    float* x = out + (size_t)row * V;
    float m = -1e30f, s = 0.f;
    for (int i = tid; i < V; i += blockDim.x) {
        float v = x[i];
        if (v > m) { s = s * expf(m - v) + 1.f; m = v; }
        else       { s += expf(v - m); }
    }
    sm[tid] = m; ss[tid] = s;
    __syncthreads();
    for (int o = 256; o; o >>= 1) {
        if (tid < o) {
            float m2 = sm[tid + o], s2 = ss[tid + o];
            float M = fmaxf(sm[tid], m2);
            ss[tid] = ss[tid] * expf(sm[tid] - M) + s2 * expf(m2 - M);
            sm[tid] = M;
        }
        __syncthreads();
    }
    if (tid == 0) lse_sh = sm[0] + logf(ss[0]);
    __syncthreads();
    float L = lse_sh;
    for (int i = tid; i < V; i += blockDim.x) x[i] -= L;
}

// ---------------- host orchestration ---------------------------------------
extern "C" void kernel_launch(void* const* d_in, const int* in_sizes, int n_in,
                              void* d_out, int out_size)
{
    const int*   facts     = (const int*)  d_in[0];
    const int*   fmask     = (const int*)  d_in[1];
    const int*   questions = (const int*)  d_in[2];
    const int*   qmask     = (const int*)  d_in[3];
    const float* embed  = (const float*)d_in[5];
    const float* igWih  = (const float*)d_in[6],  *igWhh = (const float*)d_in[7];
    const float* igbih  = (const float*)d_in[8],  *igbhh = (const float*)d_in[9];
    const float* qgWih  = (const float*)d_in[10], *qgWhh = (const float*)d_in[11];
    const float* qgbih  = (const float*)d_in[12], *qgbhh = (const float*)d_in[13];
    const float* atWih  = (const float*)d_in[14], *atWhh = (const float*)d_in[15];
    const float* atbih  = (const float*)d_in[16], *atbhh = (const float*)d_in[17];
    const float* meWih  = (const float*)d_in[18], *meWhh = (const float*)d_in[19];
    const float* mebih  = (const float*)d_in[20], *mebhh = (const float*)d_in[21];
    const float* anWih  = (const float*)d_in[22], *anWhh = (const float*)d_in[23];
    const float* anbih  = (const float*)d_in[24], *anbhh = (const float*)d_in[25];
    const float* gateW1 = (const float*)d_in[26], *gateb1 = (const float*)d_in[27];
    const float* gateW2 = (const float*)d_in[28], *gateb2 = (const float*)d_in[29];
    const float* fcW    = (const float*)d_in[30], *fcb    = (const float*)d_in[31];
    float* out = (float*)d_out;

    int Tdec = out_size / (BATCH * VOCAB);
    if (Tdec < 1) Tdec = 1;
    if (Tdec > 32) Tdec = 32;

    float *proj, *qgi, *encf, *qvec, *memb, *yq, *atgi, *angi, *uq, *ub, *gb, *hdec;
    int *flen, *qlen;
    __nv_bfloat16 *emb16, *igw16, *qgw16, *atw16, *fcw16, *encf16, *hdec16;
    __nv_bfloat16 *zq16, *zm16, *w1q16, *w1m16;
    cudaGetSymbolAddress((void**)&proj, PROJ);
    cudaGetSymbolAddress((void**)&qgi,  QGI);
    cudaGetSymbolAddress((void**)&encf, ENCF);
    cudaGetSymbolAddress((void**)&qvec, QVEC);
    cudaGetSymbolAddress((void**)&memb, MEMB);
    cudaGetSymbolAddress((void**)&yq,   YQB);
    cudaGetSymbolAddress((void**)&atgi, ATGI);
    cudaGetSymbolAddress((void**)&angi, ANGI);
    cudaGetSymbolAddress((void**)&uq,   UQB);
    cudaGetSymbolAddress((void**)&ub,   UB);
    cudaGetSymbolAddress((void**)&gb,   GBUF);
    cudaGetSymbolAddress((void**)&hdec, HDEC);
    cudaGetSymbolAddress((void**)&flen, FLENB);
    cudaGetSymbolAddress((void**)&qlen, QLENB);
    cudaGetSymbolAddress((void**)&emb16,  EMB16);
    cudaGetSymbolAddress((void**)&igw16,  IGW16);
    cudaGetSymbolAddress((void**)&qgw16,  QGW16);
    cudaGetSymbolAddress((void**)&atw16,  ATW16);
    cudaGetSymbolAddress((void**)&fcw16,  FCW16);
    cudaGetSymbolAddress((void**)&encf16, ENCF16);
    cudaGetSymbolAddress((void**)&hdec16, HDEC16);
    cudaGetSymbolAddress((void**)&zq16,   ZQ16);
    cudaGetSymbolAddress((void**)&zm16,   ZM16);
    cudaGetSymbolAddress((void**)&w1q16,  W1Q16);
    cudaGetSymbolAddress((void**)&w1m16,  W1M16);

    cudaFuncSetAttribute(gru_tc_kernel,
                         cudaFuncAttributeMaxDynamicSharedMemorySize, GRUT_SMEM_BYTES);

    // 1) lengths + weight conversions
    len_kernel<<<(NSEQF + BATCH + 255) / 256, 256>>>(fmask, qmask, flen, qlen);
    cvt_kernel<<<(VOCAB*HD/4 + 255)/256, 256>>>(embed, emb16, VOCAB*HD/4);
    cvt_kernel<<<(G3*HD/4 + 255)/256, 256>>>(igWih, igw16, G3*HD/4);
    cvt_kernel<<<(G3*HD/4 + 255)/256, 256>>>(qgWih, qgw16, G3*HD/4);
    cvt_kernel<<<(G3*HD/4 + 255)/256, 256>>>(atWih, atw16, G3*HD/4);
    cvt_kernel<<<(VOCAB*HD/4 + 255)/256, 256>>>(fcW, fcw16, VOCAB*HD/4);
    repack_w1_kernel<<<(HD*2*HD + 255)/256, 256>>>(gateW1, w1q16, w1m16);

    // 2) PROJ = embed @ ig_Wih^T + ig_bih
    {
        dim3 g((G3 + 127)/128, (VOCAB + 127)/128);
        bgemm_kernel<<<g, 256>>>(emb16, nullptr, igw16, igbih, nullptr, proj, VOCAB, G3, HD, 0);
    }
    // 3) QGI = embed[questions] @ qg_Wih^T + qg_bih
    {
        dim3 g((G3 + 127)/128, (BATCH*TQ + 127)/128);
        bgemm_kernel<<<g, 256>>>(emb16, questions, qgw16, qgbih, nullptr, qgi, BATCH*TQ, G3, HD, 0);
    }
    // 4) fact + question recurrences (tensor-core GRU, merged launch)
    gru_tc_kernel<<<NSEQF/16 + BATCH/16, 256, GRUT_SMEM_BYTES>>>(
        proj, facts, igWhh, igbhh, flen, encf,
        qgi, qgWhh, qgbhh, qlen, qvec);

    // 5) memory = q; yq = [embed[2], q]
    setup_kernel<<<(BATCH*HD + 255)/256, 256>>>(embed, qvec, memb, yq);
    cvt_kernel<<<(NSEQF*HD/4 + 255)/256, 256>>>(encf, encf16, NSEQF*HD/4);

    // 6) ATGI = enc_f @ at_Wih^T + at_bih
    {
        dim3 g((G3 + 127)/128, (NSEQF + 127)/128);
        bgemm_kernel<<<g, 256>>>(encf16, nullptr, atw16, atbih, nullptr, atgi, NSEQF, G3, HD, 0);
    }
    // 7) ANGI = yq @ an_Wih^T + an_bih
    {
        dim3 g((G3 + 127)/128, 1);
        gemm_kernel<<<g, 256>>>(yq, anWih, anbih, angi, BATCH, G3, 2*HD);
    }

    // 8) gate path: episode-invariant half once
    buildzq_kernel<<<(NSEQF*2*HD + 255)/256, 256>>>(encf, qvec, zq16);
    {
        dim3 g(1, (NSEQF + 127)/128);
        bgemm_kernel<<<g, 256>>>(zq16, nullptr, w1q16, nullptr, nullptr, uq, NSEQF, HD, 2*HD, 0);
    }

    // 9) episodic memory: 3 episodes
    for (int ep = 0; ep < EPISODES; ep++) {
        buildzm_kernel<<<(NSEQF*2*HD + 255)/256, 256>>>(encf, memb, zm16);
        {
            dim3 g(1, (NSEQF + 127)/128);
            bgemm_kernel<<<g, 256>>>(zm16, nullptr, w1m16, gateb1, uq, ub, NSEQF, HD, 2*HD, 1);
        }
        gate_kernel<<<NSEQF/8, 256>>>(ub, gateW2, gateb2, gb);
        episode_kernel<<<BATCH, G3>>>(atgi, gb, atWhh, atbhh,
                                      meWih, meWhh, mebih, mebhh, memb);
    }

    // 10) decoder hidden states + convert
    decoder_kernel<<<BATCH, G3>>>(angi, anWhh, anbhh, memb, hdec, Tdec);
    cvt_kernel<<<(BATCH*Tdec*HD/4 + 255)/256, 256>>>(hdec, hdec16, BATCH*Tdec*HD/4);

    // 11) logits into d_out + fused log-softmax
    {
        dim3 g((VOCAB + 127)/128, (BATCH*Tdec + 127)/128);
        bgemm_kernel<<<g, 256>>>(hdec16, nullptr, fcw16, fcb, nullptr, out, BATCH*Tdec, VOCAB, HD, 0);
    }
    lsesub_kernel<<<BATCH*Tdec, 512>>>(out, VOCAB);
}

// round 10
// speedup vs baseline: 2.3381x; 1.0598x over previous
#include <cuda_runtime.h>
#include <cuda_bf16.h>
#include <math.h>

#define HD     128
#define VOCAB  50000
#define BATCH  128
#define TCC    50
#define TI     32
#define TQ     32
#define NSEQF  (BATCH*TCC)     /* 6400 */
#define G3     (3*HD)          /* 384 */
#define EPISODES 3

// bgemm2: bf16 smem stride = 136 halves (272B = 68 words; 68 mod 32 = 4 -> conflict-free)
#define BST 136
#define BGEMM2_SMEM (2*128*BST*2)
// gatefused: K=256 resident, stride 264 halves (132 words; mod 32 = 4 -> conflict-free)
#define GST 264
#define GATEF_SMEM (2*128*GST*2)

// tensor-GRU smem layout
#define WB_STRIDE  136
#define GH_STRIDE  392
#define GIF_STRIDE 388
#define GRUT_SMEM_BYTES (16*GIF_STRIDE*4 + 16*GH_STRIDE*4 + 16*129*4 + 384*4 \
                         + 384*WB_STRIDE*2 + 16*WB_STRIDE*2)

// ---------------- static scratch -----------------------------------------
__device__ __align__(256) float PROJ [VOCAB*G3];
__device__ __align__(256) float QGI  [BATCH*TQ*G3];
__device__ __align__(256) float ENCF [NSEQF*HD];
__device__ __align__(256) float QVEC [BATCH*HD];
__device__ __align__(256) float MEMB [BATCH*HD];
__device__ __align__(256) float YQB  [BATCH*2*HD];
__device__ __align__(256) float ATGI [NSEQF*G3];
__device__ __align__(256) float ANGI [BATCH*G3];
__device__ __align__(256) float UQB  [NSEQF*HD];
__device__ __align__(256) float GBUF [NSEQF];
__device__ __align__(256) int   FLENB[NSEQF];
__device__ __align__(256) int   QLENB[BATCH];

__device__ __align__(256) __nv_bfloat16 EMB16 [VOCAB*HD];
__device__ __align__(256) __nv_bfloat16 IGW16 [G3*HD];
__device__ __align__(256) __nv_bfloat16 QGW16 [G3*HD];
__device__ __align__(256) __nv_bfloat16 ATW16 [G3*HD];
__device__ __align__(256) __nv_bfloat16 FCW16 [VOCAB*HD];
__device__ __align__(256) __nv_bfloat16 ENCF16[NSEQF*HD];
__device__ __align__(256) __nv_bfloat16 HDEC16[BATCH*32*HD];
__device__ __align__(256) __nv_bfloat16 ZQ16  [NSEQF*2*HD];
__device__ __align__(256) __nv_bfloat16 W1Q16 [HD*2*HD];
__device__ __align__(256) __nv_bfloat16 W1M16 [HD*2*HD];

__device__ __forceinline__ float sigf(float x) { return 1.f / (1.f + expf(-x)); }

// ---------------- merged f32 -> bf16 conversion of all weight tables --------
#define CN0 (VOCAB*HD/4)        /* embed */
#define CN1 (G3*HD/4)           /* ig/qg/at each */
__global__ void cvt_all_kernel(const float* __restrict__ embed, const float* __restrict__ igW,
                               const float* __restrict__ qgW, const float* __restrict__ atW,
                               const float* __restrict__ fcW,
                               __nv_bfloat16* __restrict__ emb16, __nv_bfloat16* __restrict__ igw16,
                               __nv_bfloat16* __restrict__ qgw16, __nv_bfloat16* __restrict__ atw16,
                               __nv_bfloat16* __restrict__ fcw16)
{
    int i = blockIdx.x * blockDim.x + threadIdx.x;
    const float* src; __nv_bfloat16* dst; int off;
    if      (i < CN0)                   { src = embed; dst = emb16; off = i; }
    else if (i < CN0 + CN1)             { src = igW;   dst = igw16; off = i - CN0; }
    else if (i < CN0 + 2*CN1)           { src = qgW;   dst = qgw16; off = i - CN0 - CN1; }
    else if (i < CN0 + 3*CN1)           { src = atW;   dst = atw16; off = i - CN0 - 2*CN1; }
    else if (i < 2*CN0 + 3*CN1)         { src = fcW;   dst = fcw16; off = i - CN0 - 3*CN1; }
    else return;
    float4 v = *(const float4*)(src + (size_t)off*4);
    __nv_bfloat16 o[4];
    o[0] = __float2bfloat16(v.x); o[1] = __float2bfloat16(v.y);
    o[2] = __float2bfloat16(v.z); o[3] = __float2bfloat16(v.w);
    *(uint2*)(dst + (size_t)off*4) = *(uint2*)o;
}

// ---------------- sequence lengths ----------------------------------------
__global__ void len_kernel(const int* __restrict__ fmask, const int* __restrict__ qmask,
                           int* __restrict__ flen, int* __restrict__ qlen)
{
    int idx = blockIdx.x * blockDim.x + threadIdx.x;
    if (idx < NSEQF) {
        int c = 0;
        #pragma unroll
        for (int t = 0; t < TI; t++) c += (fmask[idx*TI + t] == 0);
        flen[idx] = c;
    } else if (idx < NSEQF + BATCH) {
        int q = idx - NSEQF;
        int c = 0;
        #pragma unroll
        for (int t = 0; t < TQ; t++) c += (qmask[q*TQ + t] == 0);
        qlen[q] = c;
    }
}

// ---------------- bgemm2: full-K-tile resident, ldmatrix fragments ----------
// C[M,N] = act(A@B^T + bias + addC). A:[M,K] bf16 (optional gather), B:[N,K] bf16.
// K % 128 == 0.
__global__ __launch_bounds__(256)
void bgemm2_kernel(const __nv_bfloat16* __restrict__ A, const int* __restrict__ gather,
                   const __nv_bfloat16* __restrict__ B, const float* __restrict__ bias,
                   const float* __restrict__ addC, float* __restrict__ C,
                   int M, int N, int K, int act)
{
    extern __shared__ __nv_bfloat16 bsm[];
    __nv_bfloat16* As = bsm;
    __nv_bfloat16* Bs = bsm + 128*BST;
    int bm = blockIdx.y * 128, bn = blockIdx.x * 128;
    int tid = threadIdx.x;
    int warp = tid >> 5, lane = tid & 31;
    int g = lane >> 2, tg = lane & 3;
    int wm = (warp >> 2) * 64, wn = (warp & 3) * 32;
    unsigned as_b = (unsigned)__cvta_generic_to_shared(As);
    unsigned bs_b = (unsigned)__cvta_generic_to_shared(Bs);
    unsigned aoff = (unsigned)(((lane & 7) + ((lane >> 3) & 1) * 8) * BST + (lane >> 4) * 8) * 2;
    unsigned boff = (unsigned)((lane & 7) * BST + ((lane >> 3) & 1) * 8) * 2;

    float acc[4][4][4];
    #pragma unroll
    for (int mi = 0; mi < 4; mi++)
        #pragma unroll
        for (int ni = 0; ni < 4; ni++)
            #pragma unroll
            for (int r = 0; r < 4; r++) acc[mi][ni][r] = 0.f;

    for (int k0 = 0; k0 < K; k0 += 128) {
        #pragma unroll
        for (int c = 0; c < 8; c++) {
            int chunk = tid + 256*c;
            int row = chunk >> 4, kc = chunk & 15;
            int m = bm + row;
            uint4 v = make_uint4(0,0,0,0);
            if (m < M) {
                int ar = gather ? gather[m] : m;
                v = *(const uint4*)(A + (size_t)ar * K + k0 + kc*8);
            }
            *(uint4*)(As + row*BST + kc*8) = v;
        }
        #pragma unroll
        for (int c = 0; c < 8; c++) {
            int chunk = tid + 256*c;
            int row = chunk >> 4, kc = chunk & 15;
            int n = bn + row;
            uint4 v = make_uint4(0,0,0,0);
            if (n < N) v = *(const uint4*)(B + (size_t)n * K + k0 + kc*8);
            *(uint4*)(Bs + row*BST + kc*8) = v;
        }
        __syncthreads();
        #pragma unroll
        for (int ka = 0; ka < 8; ka++) {
            unsigned afr[4][4], bfr[4][2];
            #pragma unroll
            for (int mi = 0; mi < 4; mi++) {
                unsigned addr = as_b + (unsigned)(((wm + mi*16)*BST + ka*16)*2) + aoff;
                asm volatile("ldmatrix.sync.aligned.m8n8.x4.shared.b16 {%0,%1,%2,%3}, [%4];"
                    : "=r"(afr[mi][0]), "=r"(afr[mi][1]), "=r"(afr[mi][2]), "=r"(afr[mi][3])
                    : "r"(addr));
            }
            #pragma unroll
            for (int ni = 0; ni < 4; ni++) {
                unsigned addr = bs_b + (unsigned)(((wn + ni*8)*BST + ka*16)*2) + boff;
                asm volatile("ldmatrix.sync.aligned.m8n8.x2.shared.b16 {%0,%1}, [%2];"
                    : "=r"(bfr[ni][0]), "=r"(bfr[ni][1]) : "r"(addr));
            }
            #pragma unroll
            for (int mi = 0; mi < 4; mi++)
                #pragma unroll
                for (int ni = 0; ni < 4; ni++)
                    asm volatile(
                        "mma.sync.aligned.m16n8k16.row.col.f32.bf16.bf16.f32 "
                        "{%0,%1,%2,%3},{%4,%5,%6,%7},{%8,%9},{%0,%1,%2,%3};"
                        : "+f"(acc[mi][ni][0]), "+f"(acc[mi][ni][1]),
                          "+f"(acc[mi][ni][2]), "+f"(acc[mi][ni][3])
                        : "r"(afr[mi][0]), "r"(afr[mi][1]), "r"(afr[mi][2]), "r"(afr[mi][3]),
                          "r"(bfr[ni][0]), "r"(bfr[ni][1]));
        }
        __syncthreads();
    }
    #pragma unroll
    for (int mi = 0; mi < 4; mi++) {
        #pragma unroll
        for (int hh = 0; hh < 2; hh++) {
            int m = bm + wm + mi*16 + g + hh*8;
            if (m >= M) continue;
            #pragma unroll
            for (int ni = 0; ni < 4; ni++) {
                int n = bn + wn + ni*8 + tg*2;
                #pragma unroll
                for (int e = 0; e < 2; e++) {
                    int nn = n + e;
                    if (nn >= N) continue;
                    float v = acc[mi][ni][hh*2 + e];
                    if (bias) v += bias[nn];
                    if (addC) v += addC[(size_t)m * N + nn];
                    if (act == 1) v = tanhf(v);
                    C[(size_t)m * N + nn] = v;
                }
            }
        }
    }
}

// ---------------- fused gate kernel (per episode) ---------------------------
// Computes zm on the fly, u = tanh(zm@W1m^T + uq + b1), g = sigmoid(u.W2 + b2).
// One block per 128 rows; N = 128 = full output width.
__global__ __launch_bounds__(256)
void gatefused_kernel(const float* __restrict__ encf, const float* __restrict__ memb,
                      const __nv_bfloat16* __restrict__ W1m, const float* __restrict__ gateb1,
                      const float* __restrict__ uq, const float* __restrict__ W2,
                      const float* __restrict__ b2, float* __restrict__ G)
{
    extern __shared__ __nv_bfloat16 bsm2[];
    __nv_bfloat16* As = bsm2;               // [128][GST], cols 0..255 used
    __nv_bfloat16* Bs = bsm2 + 128*GST;
    __shared__ float rowsum[128];
    int bm = blockIdx.x * 128;
    int tid = threadIdx.x;
    int warp = tid >> 5, lane = tid & 31;
    int g = lane >> 2, tg = lane & 3;
    int wm = (warp >> 2) * 64, wn = (warp & 3) * 32;
    unsigned as_b = (unsigned)__cvta_generic_to_shared(As);
    unsigned bs_b = (unsigned)__cvta_generic_to_shared(Bs);
    unsigned aoff = (unsigned)(((lane & 7) + ((lane >> 3) & 1) * 8) * GST + (lane >> 4) * 8) * 2;
    unsigned boff = (unsigned)((lane & 7) * GST + ((lane >> 3) & 1) * 8) * 2;

    if (tid < 128) rowsum[tid] = 0.f;

    // stage A = [f*m | |f-m|] in bf16
    #pragma unroll
    for (int c = 0; c < 16; c++) {
        int fi = tid + 256*c;                // 4096 float4 of encf
        int row = fi >> 5, k4 = fi & 31;
        int gr = bm + row;
        int b = gr / TCC;
        float4 f = *(const float4*)(encf + (size_t)gr*HD + k4*4);
        float4 m = *(const float4*)(memb + (size_t)b*HD + k4*4);
        __nv_bfloat16 p[4], d[4];
        p[0] = __float2bfloat16(f.x*m.x); d[0] = __float2bfloat16(fabsf(f.x-m.x));
        p[1] = __float2bfloat16(f.y*m.y); d[1] = __float2bfloat16(fabsf(f.y-m.y));
        p[2] = __float2bfloat16(f.z*m.z); d[2] = __float2bfloat16(fabsf(f.z-m.z));
        p[3] = __float2bfloat16(f.w*m.w); d[3] = __float2bfloat16(fabsf(f.w-m.w));
        *(uint2*)(As + row*GST + k4*4)       = *(uint2*)p;
        *(uint2*)(As + row*GST + 128 + k4*4) = *(uint2*)d;
    }
    // stage B = W1m [128][256]
    #pragma unroll
    for (int c = 0; c < 16; c++) {
        int chunk = tid + 256*c;             // 4096 uint4
        int row = chunk >> 5, kc = chunk & 31;
        *(uint4*)(Bs + row*GST + kc*8) = *(const uint4*)(W1m + (size_t)row*256 + kc*8);
    }
    __syncthreads();

    float acc[4][4][4];
    #pragma unroll
    for (int mi = 0; mi < 4; mi++)
        #pragma unroll
        for (int ni = 0; ni < 4; ni++)
            #pragma unroll
            for (int r = 0; r < 4; r++) acc[mi][ni][r] = 0.f;

    #pragma unroll
    for (int ka = 0; ka < 16; ka++) {
        unsigned afr[4][4], bfr[4][2];
        #pragma unroll
        for (int mi = 0; mi < 4; mi++) {
            unsigned addr = as_b + (unsigned)(((wm + mi*16)*GST + ka*16)*2) + aoff;
            asm volatile("ldmatrix.sync.aligned.m8n8.x4.shared.b16 {%0,%1,%2,%3}, [%4];"
                : "=r"(afr[mi][0]), "=r"(afr[mi][1]), "=r"(afr[mi][2]), "=r"(afr[mi][3])
                : "r"(addr));
        }
        #pragma unroll
        for (int ni = 0; ni < 4; ni++) {
            unsigned addr = bs_b + (unsigned)(((wn + ni*8)*GST + ka*16)*2) + boff;
            asm volatile("ldmatrix.sync.aligned.m8n8.x2.shared.b16 {%0,%1}, [%2];"
                : "=r"(bfr[ni][0]), "=r"(bfr[ni][1]) : "r"(addr));
        }
        #pragma unroll
        for (int mi = 0; mi < 4; mi++)
            #pragma unroll
            for (int ni = 0; ni < 4; ni++)
                asm volatile(
                    "mma.sync.aligned.m16n8k16.row.col.f32.bf16.bf16.f32 "
                    "{%0,%1,%2,%3},{%4,%5,%6,%7},{%8,%9},{%0,%1,%2,%3};"
                    : "+f"(acc[mi][ni][0]), "+f"(acc[mi][ni][1]),
                      "+f"(acc[mi][ni][2]), "+f"(acc[mi][ni][3])
                    : "r"(afr[mi][0]), "r"(afr[mi][1]), "r"(afr[mi][2]), "r"(afr[mi][3]),
                      "r"(bfr[ni][0]), "r"(bfr[ni][1]));
    }
    __syncthreads();

    // epilogue: tanh, dot with W2, reduce per row, sigmoid
    #pragma unroll
    for (int mi = 0; mi < 4; mi++) {
        #pragma unroll
        for (int hh = 0; hh < 2; hh++) {
            int m = wm + mi*16 + g + hh*8;     // local row 0..127
            float s = 0.f;
            #pragma unroll
            for (int ni = 0; ni < 4; ni++) {
                #pragma unroll
                for (int e = 0; e < 2; e++) {
                    int n = wn + ni*8 + tg*2 + e;
                    float v = acc[mi][ni][hh*2 + e] + gateb1[n]
                            + uq[(size_t)(bm + m) * HD + n];
                    s += tanhf(v) * W2[n];
                }
            }
            s += __shfl_xor_sync(0xffffffffu, s, 1);
            s += __shfl_xor_sync(0xffffffffu, s, 2);
            if (tg == 0) atomicAdd(&rowsum[m], s);
        }
    }
    __syncthreads();
    if (tid < 128) G[bm + tid] = sigf(rowsum[tid] + b2[0]);
}

// ---------------- tensor-core multi-step GRU --------------------------------
__global__ __launch_bounds__(256)
void gru_tc_kernel(const float* __restrict__ proj, const int* __restrict__ facts,
                   const float* __restrict__ igWhh, const float* __restrict__ igbhh,
                   const int* __restrict__ flen, float* __restrict__ encf,
                   __nv_bfloat16* __restrict__ encf16,
                   const float* __restrict__ qgi, const float* __restrict__ qgWhh,
                   const float* __restrict__ qgbhh, const int* __restrict__ qlen,
                   float* __restrict__ qvec)
{
    extern __shared__ __align__(16) unsigned char smraw[];
    float* gif = (float*)smraw;
    float* ghf = gif + 16*GIF_STRIDE;
    float* hfp = ghf + 16*GH_STRIDE;
    float* bsh = hfp + 16*129;
    __nv_bfloat16* Wsh = (__nv_bfloat16*)(bsh + 384);
    __nv_bfloat16* hb  = Wsh + 384*WB_STRIDE;
    __shared__ int len_sh[16];

    const int nb_f = NSEQF/16;
    bool isq = (blockIdx.x >= nb_f);
    const float* gi_tab = isq ? qgi   : proj;
    const int*   tokens = isq ? (const int*)0 : facts;
    const float* Whh    = isq ? qgWhh : igWhh;
    const float* bhh    = isq ? qgbhh : igbhh;
    const int*   lens   = isq ? qlen  : flen;
    float*       encout = isq ? qvec  : encf;
    int base = (isq ? (blockIdx.x - nb_f) : blockIdx.x) * 16;
    const int T = 32;

    int tid = threadIdx.x;
    int warp = tid >> 5, lane = tid & 31;
    int g = lane >> 2, tg = lane & 3;
    int wn = warp * 48;

    for (int idx = tid; idx < 384*32; idx += 256) {
        int r = idx >> 5, c4 = idx & 31;
        float4 v = *(const float4*)(Whh + (size_t)r*HD + c4*4);
        __nv_bfloat16 o[4];
        o[0] = __float2bfloat16(v.x); o[1] = __float2bfloat16(v.y);
        o[2] = __float2bfloat16(v.z); o[3] = __float2bfloat16(v.w);
        *(uint2*)(Wsh + r*WB_STRIDE + c4*4) = *(uint2*)o;
    }
    for (int i = tid; i < 384; i += 256) bsh[i] = bhh[i];
    for (int i = tid; i < 16*129; i += 256) hfp[i] = 0.f;
    for (int i = tid; i < 16*WB_STRIDE; i += 256) hb[i] = __float2bfloat16(0.f);
    if (tid < 16) len_sh[tid] = lens[base + tid];
    __syncthreads();

    int ps = tid >> 4;
    int pj = (tid & 15) * 8;

    for (int t = 0; t < T; t++) {
        for (int i = tid; i < 16*96; i += 256) {
            int s = i / 96, c4 = i % 96;
            size_t srow;
            if (tokens) {
                int tok = tokens[(size_t)(base + s) * T + t];
                srow = (size_t)tok * G3;
            } else {
                srow = (size_t)((base + s) * T + t) * G3;
            }
            *(float4*)(gif + s*GIF_STRIDE + c4*4) =
                *(const float4*)(gi_tab + srow + c4*4);
        }

        float acc[6][4];
        #pragma unroll
        for (int ni = 0; ni < 6; ni++)
            #pragma unroll
            for (int r = 0; r < 4; r++) acc[ni][r] = 0.f;

        #pragma unroll
        for (int ka = 0; ka < 8; ka++) {
            const __nv_bfloat16* ap = hb + ka*16;
            unsigned a0 = *(const unsigned*)(ap + g*WB_STRIDE + tg*2);
            unsigned a1 = *(const unsigned*)(ap + (g+8)*WB_STRIDE + tg*2);
            unsigned a2 = *(const unsigned*)(ap + g*WB_STRIDE + 8 + tg*2);
            unsigned a3 = *(const unsigned*)(ap + (g+8)*WB_STRIDE + 8 + tg*2);
            #pragma unroll
            for (int ni = 0; ni < 6; ni++) {
                const __nv_bfloat16* bp = Wsh + (wn + ni*8 + g)*WB_STRIDE + ka*16 + tg*2;
                unsigned b0 = *(const unsigned*)bp;
                unsigned b1 = *(const unsigned*)(bp + 8);
                asm volatile(
                    "mma.sync.aligned.m16n8k16.row.col.f32.bf16.bf16.f32 "
                    "{%0,%1,%2,%3},{%4,%5,%6,%7},{%8,%9},{%0,%1,%2,%3};"
                    : "+f"(acc[ni][0]), "+f"(acc[ni][1]),
                      "+f"(acc[ni][2]), "+f"(acc[ni][3])
                    : "r"(a0), "r"(a1), "r"(a2), "r"(a3), "r"(b0), "r"(b1));
            }
        }
        #pragma unroll
        for (int ni = 0; ni < 6; ni++) {
            int n = wn + ni*8 + tg*2;
            ghf[g*GH_STRIDE + n]         = acc[ni][0];
            ghf[g*GH_STRIDE + n + 1]     = acc[ni][1];
            ghf[(g+8)*GH_STRIDE + n]     = acc[ni][2];
            ghf[(g+8)*GH_STRIDE + n + 1] = acc[ni][3];
        }
        __syncthreads();

        {
            int L = len_sh[ps];
            int tlast = (L > 0) ? (L - 1) : 0;
            const float* gi_s = gif + ps*GIF_STRIDE;
            const float* gh_s = ghf + ps*GH_STRIDE;
            float* hrow = hfp + ps*129;
            __nv_bfloat16* hbrow = hb + ps*WB_STRIDE;
            #pragma unroll
            for (int jj = 0; jj < 8; jj++) {
                int j = pj + jj;
                float r = sigf(gi_s[j]        + gh_s[j]        + bsh[j]);
                float z = sigf(gi_s[HD + j]   + gh_s[HD + j]   + bsh[HD + j]);
                float n = tanhf(gi_s[2*HD + j] + r * (gh_s[2*HD + j] + bsh[2*HD + j]));
                float hold = hrow[j];
                float hnew = (1.f - z) * n + z * hold;
                hrow[j] = hnew;
                hbrow[j] = __float2bfloat16(hnew);
                if (t == tlast) {
                    encout[(size_t)(base + ps) * HD + j] = hnew;
                    if (!isq) encf16[(size_t)(base + ps) * HD + j] = __float2bfloat16(hnew);
                }
            }
        }
        __syncthreads();
    }
}

// ---------------- fp32 SIMT GEMM (small: ANGI) ------------------------------
__global__ void gemm_kernel(const float* __restrict__ A, const float* __restrict__ B,
                            const float* __restrict__ bias, float* __restrict__ C,
                            int M, int N, int K)
{
    const int BM = 128, BN = 128, BK = 16;
    __shared__ __align__(16) float As[BK][BM];
    __shared__ __align__(16) float Bs[BK][BN];
    int bm = blockIdx.y * BM, bn = blockIdx.x * BN;
    int tid = threadIdx.x;
    int tx = tid & 15, ty = tid >> 4;
    int lr = tid >> 1;
    int lk = (tid & 1) * 4;

    float acc[8][8];
    #pragma unroll
    for (int i = 0; i < 8; i++)
        #pragma unroll
        for (int j = 0; j < 8; j++) acc[i][j] = 0.f;

    for (int k0 = 0; k0 < K; k0 += BK) {
        {
            int m = bm + lr;
            float4 v0 = make_float4(0.f,0.f,0.f,0.f), v1 = v0;
            if (m < M) {
                const float* ap = A + (size_t)m * K + k0;
                v0 = *(const float4*)(ap + lk);
                v1 = *(const float4*)(ap + lk + 8);
            }
            As[lk+0][lr]=v0.x; As[lk+1][lr]=v0.y; As[lk+2][lr]=v0.z; As[lk+3][lr]=v0.w;
            As[lk+8][lr]=v1.x; As[lk+9][lr]=v1.y; As[lk+10][lr]=v1.z; As[lk+11][lr]=v1.w;
        }
        {
            int n = bn + lr;
            float4 v0 = make_float4(0.f,0.f,0.f,0.f), v1 = v0;
            if (n < N) {
                const float* bp = B + (size_t)n * K + k0;
                v0 = *(const float4*)(bp + lk);
                v1 = *(const float4*)(bp + lk + 8);
            }
            Bs[lk+0][lr]=v0.x; Bs[lk+1][lr]=v0.y; Bs[lk+2][lr]=v0.z; Bs[lk+3][lr]=v0.w;
            Bs[lk+8][lr]=v1.x; Bs[lk+9][lr]=v1.y; Bs[lk+10][lr]=v1.z; Bs[lk+11][lr]=v1.w;
        }
        __syncthreads();
        #pragma unroll
        for (int k = 0; k < BK; k++) {
            float a[8], b[8];
            *(float4*)&a[0] = *(const float4*)&As[k][ty*8];
            *(float4*)&a[4] = *(const float4*)&As[k][ty*8 + 4];
            *(float4*)&b[0] = *(const float4*)&Bs[k][tx*8];
            *(float4*)&b[4] = *(const float4*)&Bs[k][tx*8 + 4];
            #pragma unroll
            for (int i = 0; i < 8; i++)
                #pragma unroll
                for (int j = 0; j < 8; j++)
                    acc[i][j] = fmaf(a[i], b[j], acc[i][j]);
        }
        __syncthreads();
    }
    #pragma unroll
    for (int i = 0; i < 8; i++) {
        int m = bm + ty*8 + i;
        if (m >= M) continue;
        #pragma unroll
        for (int j = 0; j < 8; j++) {
            int n = bn + tx*8 + j;
            if (n >= N) continue;
            float v = acc[i][j];
            if (bias) v += bias[n];
            C[(size_t)m * N + n] = v;
        }
    }
}

// ---------------- setup + small kernels ------------------------------------
__global__ void setup_kernel(const float* __restrict__ embed, const float* __restrict__ qvec,
                             float* __restrict__ mem, float* __restrict__ yq)
{
    int idx = blockIdx.x * blockDim.x + threadIdx.x;
    if (idx >= BATCH * HD) return;
    int b = idx / HD, j = idx % HD;
    float qv = qvec[idx];
    mem[idx] = qv;
    yq[b*2*HD + j]      = embed[2*HD + j];
    yq[b*2*HD + HD + j] = qv;
}

__global__ void repack_w1_kernel(const float* __restrict__ W1,
                                 __nv_bfloat16* __restrict__ W1q,
                                 __nv_bfloat16* __restrict__ W1m)
{
    int idx = blockIdx.x * blockDim.x + threadIdx.x;
    if (idx >= HD * 2*HD) return;
    int o = idx >> 8, c = idx & 255;
    int cq = (c < HD) ? c : (2*HD + (c - HD));
    int cm = (c < HD) ? (HD + c) : (3*HD + (c - HD));
    W1q[idx] = __float2bfloat16(W1[o*4*HD + cq]);
    W1m[idx] = __float2bfloat16(W1[o*4*HD + cm]);
}

__global__ void buildzq_kernel(const float* __restrict__ encf, const float* __restrict__ q,
                               __nv_bfloat16* __restrict__ zq)
{
    int idx = blockIdx.x * blockDim.x + threadIdx.x;
    if (idx >= NSEQF * 2*HD) return;
    int row = idx >> 8, c = idx & 255, j = c & (HD-1), b = row / TCC;
    float f  = encf[row*HD + j];
    float qv = q[b*HD + j];
    zq[idx] = __float2bfloat16((c < HD) ? f * qv : fabsf(f - qv));
}

// ---------------- episode scan + memory GRU --------------------------------
__global__ void episode_kernel(const float* __restrict__ atgi, const float* __restrict__ gate,
                               const float* __restrict__ Whh, const float* __restrict__ bhh,
                               const float* __restrict__ meWih, const float* __restrict__ meWhh,
                               const float* __restrict__ mebih, const float* __restrict__ mebhh,
                               float* __restrict__ mem)
{
    __shared__ __align__(16) float h_sh[HD];
    __shared__ __align__(16) float msh[HD];
    __shared__ float rr[HD], zz[HD], gin[HD], ghn[HD];
    int b = blockIdx.x, g = threadIdx.x;
    int j = g & (HD - 1);
    if (g < HD) h_sh[g] = 0.f;
    __syncthreads();
    float bh = bhh[g];
    const float4* wr = (const float4*)(Whh + g * HD);

    for (int tc = 0; tc < TCC; tc++) {
        float gi = atgi[(size_t)(b*TCC + tc) * G3 + g];
        float gh = bh;
        #pragma unroll 8
        for (int kc = 0; kc < HD/4; kc++) {
            float4 w = __ldg(&wr[kc]);
            float4 h4 = *(const float4*)&h_sh[kc*4];
            gh = fmaf(w.x, h4.x, gh); gh = fmaf(w.y, h4.y, gh);
            gh = fmaf(w.z, h4.z, gh); gh = fmaf(w.w, h4.w, gh);
        }
        float v = gi + gh;
        if      (g < HD)   rr[j] = sigf(v);
        else if (g < 2*HD) zz[j] = sigf(v);
        else { gin[j] = gi; ghn[j] = gh; }
        __syncthreads();
        if (g < HD) {
            float r = rr[g], z = zz[g];
            float n = tanhf(gin[g] + r * ghn[g]);
            float h2 = (1.f - z) * n + z * h_sh[g];
            float gd = gate[b*TCC + tc];
            h_sh[g] = gd * h2 + (1.f - gd) * h_sh[g];
        }
        __syncthreads();
    }
    if (g < HD) msh[g] = mem[b*HD + g];
    __syncthreads();
    {
        float gi = mebih[g], gh = mebhh[g];
        const float4* wi = (const float4*)(meWih + g * HD);
        const float4* wh = (const float4*)(meWhh + g * HD);
        #pragma unroll 8
        for (int kc = 0; kc < HD/4; kc++) {
            float4 a = __ldg(&wi[kc]);
            float4 e4 = *(const float4*)&h_sh[kc*4];
            gi = fmaf(a.x, e4.x, gi); gi = fmaf(a.y, e4.y, gi);
            gi = fmaf(a.z, e4.z, gi); gi = fmaf(a.w, e4.w, gi);
            float4 c = __ldg(&wh[kc]);
            float4 m4 = *(const float4*)&msh[kc*4];
            gh = fmaf(c.x, m4.x, gh); gh = fmaf(c.y, m4.y, gh);
            gh = fmaf(c.z, m4.z, gh); gh = fmaf(c.w, m4.w, gh);
        }
        float v = gi + gh;
        if      (g < HD)   rr[j] = sigf(v);
        else if (g < 2*HD) zz[j] = sigf(v);
        else { gin[j] = gi; ghn[j] = gh; }
    }
    __syncthreads();
    if (g < HD) {
        float r = rr[g], z = zz[g];
        float n = tanhf(gin[g] + r * ghn[g]);
        mem[b*HD + g] = (1.f - z) * n + z * msh[g];
    }
}

// ---------------- decoder scan (writes bf16 directly) ------------------------
__global__ void decoder_kernel(const float* __restrict__ angi, const float* __restrict__ Whh,
                               const float* __restrict__ bhh, const float* __restrict__ mem,
                               __nv_bfloat16* __restrict__ hdec16, int Tdec)
{
    __shared__ __align__(16) float h_sh[HD];
    __shared__ float rr[HD], zz[HD], gin[HD], ghn[HD];
    int b = blockIdx.x, g = threadIdx.x;
    int j = g & (HD - 1);
    if (g < HD) h_sh[g] = mem[b*HD + g];
    __syncthreads();
    float gi = angi[(size_t)b * G3 + g];
    float bh = bhh[g];
    const float4* wr = (const float4*)(Whh + g * HD);

    for (int t = 0; t < Tdec; t++) {
        float gh = bh;
        #pragma unroll 8
        for (int kc = 0; kc < HD/4; kc++) {
            float4 w = __ldg(&wr[kc]);
            float4 h4 = *(const float4*)&h_sh[kc*4];
            gh = fmaf(w.x, h4.x, gh); gh = fmaf(w.y, h4.y, gh);
            gh = fmaf(w.z, h4.z, gh); gh = fmaf(w.w, h4.w, gh);
        }
        float v = gi + gh;
        if      (g < HD)   rr[j] = sigf(v);
        else if (g < 2*HD) zz[j] = sigf(v);
        else { gin[j] = gi; ghn[j] = gh; }
        __syncthreads();
        if (g < HD) {
            float r = rr[g], z = zz[g];
            float n = tanhf(gin[g] + r * ghn[g]);
            float hn = (1.f - z) * n + z * h_sh[g];
            h_sh[g] = hn;
            hdec16[(size_t)(b*Tdec + t) * HD + g] = __float2bfloat16(hn);
        }
        __syncthreads();
    }
}

// ---------------- fused log-softmax ----------------------------------------
__global__ void lsesub_kernel(float* __restrict__ out, int V)
{
    __shared__ float sm[512], ss[512];
    __shared__ float lse_sh;
    int row = blockIdx.x, tid = threadIdx.x;
    float* x = out + (size_t)row * V;
    float m = -1e30f, s = 0.f;
    for (int i = tid; i < V; i += blockDim.x) {
        float v = x[i];
        if (v > m) { s = s * expf(m - v) + 1.f; m = v; }
        else       { s += expf(v - m); }
    }
    sm[tid] = m; ss[tid] = s;
    __syncthreads();
    for (int o = 256; o; o >>= 1) {
        if (tid < o) {
            float m2 = sm[tid + o], s2 = ss[tid + o];
            float M = fmaxf(sm[tid], m2);
            ss[tid] = ss[tid] * expf(sm[tid] - M) + s2 * expf(m2 - M);
            sm[tid] = M;
        }
        __syncthreads();
    }
    if (tid == 0) lse_sh = sm[0] + logf(ss[0]);
    __syncthreads();
    float L = lse_sh;
    for (int i = tid; i < V; i += blockDim.x) x[i] -= L;
}

// ---------------- host orchestration ---------------------------------------
extern "C" void kernel_launch(void* const* d_in, const int* in_sizes, int n_in,
                              void* d_out, int out_size)
{
    const int*   facts     = (const int*)  d_in[0];
    const int*   fmask     = (const int*)  d_in[1];
    const int*   questions = (const int*)  d_in[2];
    const int*   qmask     = (const int*)  d_in[3];
    const float* embed  = (const float*)d_in[5];
    const float* igWih  = (const float*)d_in[6],  *igWhh = (const float*)d_in[7];
    const float* igbih  = (const float*)d_in[8],  *igbhh = (const float*)d_in[9];
    const float* qgWih  = (const float*)d_in[10], *qgWhh = (const float*)d_in[11];
    const float* qgbih  = (const float*)d_in[12], *qgbhh = (const float*)d_in[13];
    const float* atWih  = (const float*)d_in[14], *atWhh = (const float*)d_in[15];
    const float* atbih  = (const float*)d_in[16], *atbhh = (const float*)d_in[17];
    const float* meWih  = (const float*)d_in[18], *meWhh = (const float*)d_in[19];
    const float* mebih  = (const float*)d_in[20], *mebhh = (const float*)d_in[21];
    const float* anWih  = (const float*)d_in[22], *anWhh = (const float*)d_in[23];
    const float* anbih  = (const float*)d_in[24], *anbhh = (const float*)d_in[25];
    const float* gateW1 = (const float*)d_in[26], *gateb1 = (const float*)d_in[27];
    const float* gateW2 = (const float*)d_in[28], *gateb2 = (const float*)d_in[29];
    const float* fcW    = (const float*)d_in[30], *fcb    = (const float*)d_in[31];
    float* out = (float*)d_out;

    int Tdec = out_size / (BATCH * VOCAB);
    if (Tdec < 1) Tdec = 1;
    if (Tdec > 32) Tdec = 32;

    float *proj, *qgi, *encf, *qvec, *memb, *yq, *atgi, *angi, *uq, *gb;
    int *flen, *qlen;
    __nv_bfloat16 *emb16, *igw16, *qgw16, *atw16, *fcw16, *encf16, *hdec16;
    __nv_bfloat16 *zq16, *w1q16, *w1m16;
    cudaGetSymbolAddress((void**)&proj, PROJ);
    cudaGetSymbolAddress((void**)&qgi,  QGI);
    cudaGetSymbolAddress((void**)&encf, ENCF);
    cudaGetSymbolAddress((void**)&qvec, QVEC);
    cudaGetSymbolAddress((void**)&memb, MEMB);
    cudaGetSymbolAddress((void**)&yq,   YQB);
    cudaGetSymbolAddress((void**)&atgi, ATGI);
    cudaGetSymbolAddress((void**)&angi, ANGI);
    cudaGetSymbolAddress((void**)&uq,   UQB);
    cudaGetSymbolAddress((void**)&gb,   GBUF);
    cudaGetSymbolAddress((void**)&flen, FLENB);
    cudaGetSymbolAddress((void**)&qlen, QLENB);
    cudaGetSymbolAddress((void**)&emb16,  EMB16);
    cudaGetSymbolAddress((void**)&igw16,  IGW16);
    cudaGetSymbolAddress((void**)&qgw16,  QGW16);
    cudaGetSymbolAddress((void**)&atw16,  ATW16);
    cudaGetSymbolAddress((void**)&fcw16,  FCW16);
    cudaGetSymbolAddress((void**)&encf16, ENCF16);
    cudaGetSymbolAddress((void**)&hdec16, HDEC16);
    cudaGetSymbolAddress((void**)&zq16,   ZQ16);
    cudaGetSymbolAddress((void**)&w1q16,  W1Q16);
    cudaGetSymbolAddress((void**)&w1m16,  W1M16);

    cudaFuncSetAttribute(gru_tc_kernel,
                         cudaFuncAttributeMaxDynamicSharedMemorySize, GRUT_SMEM_BYTES);
    cudaFuncSetAttribute(bgemm2_kernel,
                         cudaFuncAttributeMaxDynamicSharedMemorySize, BGEMM2_SMEM);
    cudaFuncSetAttribute(gatefused_kernel,
                         cudaFuncAttributeMaxDynamicSharedMemorySize, GATEF_SMEM);

    // 1) merged conversions
    {
        int n4 = 2*CN0 + 3*CN1;
        cvt_all_kernel<<<(n4 + 255)/256, 256>>>(embed, igWih, qgWih, atWih, fcW,
                                                emb16, igw16, qgw16, atw16, fcw16);
    }
    // 2) lengths
    len_kernel<<<(NSEQF + BATCH + 255)/256, 256>>>(fmask, qmask, flen, qlen);
    // 3) gate weight repack
    repack_w1_kernel<<<(HD*2*HD + 255)/256, 256>>>(gateW1, w1q16, w1m16);

    // 4) PROJ = embed @ ig_Wih^T + ig_bih   <-- ncu-profiled launch
    {
        dim3 g(3, (VOCAB + 127)/128);
        bgemm2_kernel<<<g, 256, BGEMM2_SMEM>>>(emb16, nullptr, igw16, igbih, nullptr,
                                               proj, VOCAB, G3, HD, 0);
    }
    // 5) QGI = embed[questions] @ qg_Wih^T + qg_bih
    {
        dim3 g(3, (BATCH*TQ + 127)/128);
        bgemm2_kernel<<<g, 256, BGEMM2_SMEM>>>(emb16, questions, qgw16, qgbih, nullptr,
                                               qgi, BATCH*TQ, G3, HD, 0);
    }
    // 6) fact + question recurrences
    gru_tc_kernel<<<NSEQF/16 + BATCH/16, 256, GRUT_SMEM_BYTES>>>(
        proj, facts, igWhh, igbhh, flen, encf, encf16,
        qgi, qgWhh, qgbhh, qlen, qvec);

    // 7) memory = q; yq = [embed[2], q]
    setup_kernel<<<(BATCH*HD + 255)/256, 256>>>(embed, qvec, memb, yq);

    // 8) ATGI = enc_f @ at_Wih^T + at_bih
    {
        dim3 g(3, (NSEQF + 127)/128);
        bgemm2_kernel<<<g, 256, BGEMM2_SMEM>>>(encf16, nullptr, atw16, atbih, nullptr,
                                               atgi, NSEQF, G3, HD, 0);
    }
    // 9) ANGI = yq @ an_Wih^T + an_bih
    {
        dim3 g(3, 1);
        gemm_kernel<<<g, 256>>>(yq, anWih, anbih, angi, BATCH, G3, 2*HD);
    }

    // 10-11) gate path: episode-invariant half once
    buildzq_kernel<<<(NSEQF*2*HD + 255)/256, 256>>>(encf, qvec, zq16);
    {
        dim3 g(1, NSEQF/128);
        bgemm2_kernel<<<g, 256, BGEMM2_SMEM>>>(zq16, nullptr, w1q16, nullptr, nullptr,
                                               uq, NSEQF, HD, 2*HD, 0);
    }

    // 12-17) episodic memory: 3 episodes (fused gate + scan)
    for (int ep = 0; ep < EPISODES; ep++) {
        gatefused_kernel<<<NSEQF/128, 256, GATEF_SMEM>>>(encf, memb, w1m16, gateb1,
                                                         uq, gateW2, gateb2, gb);
        episode_kernel<<<BATCH, G3>>>(atgi, gb, atWhh, atbhh,
                                      meWih, meWhh, mebih, mebhh, memb);
    }

    // 18) decoder hidden states (bf16 direct)
    decoder_kernel<<<BATCH, G3>>>(angi, anWhh, anbhh, memb, hdec16, Tdec);

    // 19) logits into d_out
    {
        dim3 g((VOCAB + 127)/128, (BATCH*Tdec + 127)/128);
        bgemm2_kernel<<<g, 256, BGEMM2_SMEM>>>(hdec16, nullptr, fcw16, fcb, nullptr,
                                               out, BATCH*Tdec, VOCAB, HD, 0);
    }
    // 20) fused log-softmax
    lsesub_kernel<<<BATCH*Tdec, 512>>>(out, VOCAB);
}